// round 12
// baseline (speedup 1.0000x reference)
#include <cuda_runtime.h>
#include <cuda_bf16.h>
#include <cstdint>

// Problem constants
#define B    32
#define SX   512
#define SM_  4096
#define D    256
#define TOPK 5
#define NCAND 16

#define NEG_INF (__int_as_float(0xff800000))

// GEMM tiling
#define MT   128          // mem rows per CTA
#define NC   128          // query chunk
#define NCH  (SX / NC)    // 4 chunks
#define KSTEPS (D / 16)   // 16 k-steps of 16
#define STRIDE 264        // bf16 elems per smem row (528B: 16B aligned, 4-bank stagger)
#define NTHREADS 512

// Scratch (no allocations allowed)
__device__ float g_inv_na[B * SX];
__device__ float g_simmax[B * SM_];
__device__ int   g_cand[B * NCAND];
__device__ float g_score[B * NCAND];
__device__ int   g_done1[B];   // GEMM CTAs per batch  (zero-init; reset each call)
__device__ int   g_done2[B];   // rerank CTAs per batch
__device__ __nv_bfloat16 g_xbf[B * SX * D];    // 8 MB

// ---------------------------------------------------------------------------
// helpers
// ---------------------------------------------------------------------------
__device__ __forceinline__ uint32_t smem_u32(const void* p) {
    return (uint32_t)__cvta_generic_to_shared(p);
}

__device__ __forceinline__ uint32_t pack_bf2(float a, float b) {
    __nv_bfloat162 h = __float22bfloat162_rn(make_float2(a, b));
    return *reinterpret_cast<uint32_t*>(&h);
}

__device__ __forceinline__ void cp16(uint32_t dst, const void* src) {
    asm volatile("cp.async.cg.shared.global [%0], [%1], 16;" :: "r"(dst), "l"(src));
}
__device__ __forceinline__ void cp_commit() {
    asm volatile("cp.async.commit_group;" ::: "memory");
}
__device__ __forceinline__ void cp_wait0() {
    asm volatile("cp.async.wait_group 0;" ::: "memory");
}

__device__ __forceinline__ void ldsm_x4(uint32_t& r0, uint32_t& r1,
                                        uint32_t& r2, uint32_t& r3, uint32_t addr) {
    asm volatile("ldmatrix.sync.aligned.m8n8.x4.shared.b16 {%0,%1,%2,%3}, [%4];"
                 : "=r"(r0), "=r"(r1), "=r"(r2), "=r"(r3) : "r"(addr));
}

__device__ __forceinline__ void mma_bf16(float& c0, float& c1, float& c2, float& c3,
                                         uint32_t a0, uint32_t a1, uint32_t a2, uint32_t a3,
                                         uint32_t b0, uint32_t b1) {
    asm volatile(
        "mma.sync.aligned.m16n8k16.row.col.f32.bf16.bf16.f32 "
        "{%0,%1,%2,%3}, {%4,%5,%6,%7}, {%8,%9}, {%0,%1,%2,%3};"
        : "+f"(c0), "+f"(c1), "+f"(c2), "+f"(c3)
        : "r"(a0), "r"(a1), "r"(a2), "r"(a3), "r"(b0), "r"(b1));
}

__device__ __forceinline__ float dot8(const float4& a0, const float4& a1,
                                      const float4& b0, const float4& b1) {
    float s = a0.x * b0.x;
    s = fmaf(a0.y, b0.y, s);
    s = fmaf(a0.z, b0.z, s);
    s = fmaf(a0.w, b0.w, s);
    s = fmaf(a1.x, b1.x, s);
    s = fmaf(a1.y, b1.y, s);
    s = fmaf(a1.z, b1.z, s);
    s = fmaf(a1.w, b1.w, s);
    return s;
}

// ---------------------------------------------------------------------------
// 1) x: inverse L2 norm + bf16 conversion ; also resets the done-counters
// ---------------------------------------------------------------------------
__global__ void invnorm_x_kernel(const float* __restrict__ in) {
    if (blockIdx.x == 0 && threadIdx.x < 2 * B) {
        if (threadIdx.x < B) g_done1[threadIdx.x] = 0;
        else                 g_done2[threadIdx.x - B] = 0;
    }
    int gwarp = (blockIdx.x * blockDim.x + threadIdx.x) >> 5;
    int lane  = threadIdx.x & 31;
    if (gwarp >= B * SX) return;
    const float4* r = reinterpret_cast<const float4*>(in + (size_t)gwarp * D);
    float4 v0 = r[lane];
    float4 v1 = r[lane + 32];

    __nv_bfloat16* dst = g_xbf + (size_t)gwarp * D;
    uint2 wa = make_uint2(pack_bf2(v0.x, v0.y), pack_bf2(v0.z, v0.w));
    uint2 wb = make_uint2(pack_bf2(v1.x, v1.y), pack_bf2(v1.z, v1.w));
    reinterpret_cast<uint64_t*>(dst)[lane]      = *reinterpret_cast<uint64_t*>(&wa);
    reinterpret_cast<uint64_t*>(dst)[lane + 32] = *reinterpret_cast<uint64_t*>(&wb);

    float s = v0.x * v0.x + v0.y * v0.y + v0.z * v0.z + v0.w * v0.w
            + v1.x * v1.x + v1.y * v1.y + v1.z * v1.z + v1.w * v1.w;
#pragma unroll
    for (int off = 16; off; off >>= 1)
        s += __shfl_xor_sync(0xffffffffu, s, off);
    if (lane == 0) g_inv_na[gwarp] = rsqrtf(s);
}

// ---------------------------------------------------------------------------
// 2) fused tensor sim-max + last-CTA-per-batch approximate top-16.
// ---------------------------------------------------------------------------
__device__ __forceinline__ void load_tile_async(uint32_t sdst,
                                                const __nv_bfloat16* gsrc, int tid) {
#pragma unroll
    for (int i = tid; i < MT * 32; i += NTHREADS) {
        const int r = i >> 5, c = i & 31;
        cp16(sdst + (uint32_t)(r * (STRIDE * 2) + c * 16), gsrc + (size_t)r * D + c * 8);
    }
}

__global__ __launch_bounds__(NTHREADS, 1)
void simmax_mma_kernel(const float* __restrict__ mem) {
    extern __shared__ char smem[];
    __nv_bfloat16* sA  = reinterpret_cast<__nv_bfloat16*>(smem);   // [128][STRIDE]
    __nv_bfloat16* sB0 = sA + MT * STRIDE;
    __nv_bfloat16* sB1 = sB0 + NC * STRIDE;
    float* s_ina = reinterpret_cast<float*>(sB1 + NC * STRIDE);    // [512]
    float* s_inb = s_ina + SX;                                     // [128]
    float* red   = s_inb + MT;                                     // [4*128]

    __shared__ float swv[16];
    __shared__ int   swi[16];
    __shared__ int   s_win;
    __shared__ int   s_old;

    const int tid    = threadIdx.x;
    const int wid    = tid >> 5;
    const int lane   = tid & 31;
    const int b      = blockIdx.y;
    const int m0     = blockIdx.x * MT;
    const int warp_m = wid & 3;
    const int warp_n = wid >> 2;

    const float* Ag = mem + ((size_t)b * SM_ + m0) * D;
    const __nv_bfloat16* Xg = g_xbf + (size_t)b * SX * D;

    load_tile_async(smem_u32(sB0), Xg, tid);
    cp_commit();

    // A tile: fp32 LDG -> bf16 STS. 128 rows x 64 float4 = 8192 ops.
#pragma unroll
    for (int j = 0; j < 16; ++j) {
        const int idx = j * NTHREADS + tid;
        const int r = idx >> 6, q = idx & 63;
        float4 v = reinterpret_cast<const float4*>(Ag)[(size_t)r * 64 + q];
        uint2 w = make_uint2(pack_bf2(v.x, v.y), pack_bf2(v.z, v.w));
        *reinterpret_cast<uint2*>(
            reinterpret_cast<char*>(sA) + r * (STRIDE * 2) + q * 8) = w;
    }
#pragma unroll
    for (int i = tid; i < SX; i += NTHREADS) s_ina[i] = g_inv_na[b * SX + i];
    __syncthreads();

    // per-row inv norms from the bf16 A tile: 4 threads per row
    {
        const int r  = tid >> 2;
        const int q0 = (tid & 3) * 64;
        const __nv_bfloat16* row = sA + r * STRIDE + q0;
        float s = 0.0f;
#pragma unroll
        for (int k = 0; k < 32; ++k) {
            float2 p = __bfloat1622float2(
                *reinterpret_cast<const __nv_bfloat162*>(row + 2 * k));
            s = fmaf(p.x, p.x, fmaf(p.y, p.y, s));
        }
        s += __shfl_xor_sync(0xffffffffu, s, 1);
        s += __shfl_xor_sync(0xffffffffu, s, 2);
        if ((tid & 3) == 0) s_inb[r] = rsqrtf(s);
    }
    cp_wait0();
    __syncthreads();

    const int g = lane >> 3, r8 = lane & 7;
    const uint32_t aA = smem_u32(sA) +
        (uint32_t)(((warp_m * 32 + (g & 1) * 8 + r8) * STRIDE + (g >> 1) * 8) * 2);
    const uint32_t aBoff =
        (uint32_t)(((warp_n * 32 + (g >> 1) * 8 + r8) * STRIDE + (g & 1) * 8) * 2);
    const uint32_t aBbuf[2] = { smem_u32(sB0) + aBoff, smem_u32(sB1) + aBoff };
    const uint32_t sBbuf[2] = { smem_u32(sB0), smem_u32(sB1) };

    float rmax[2][2];
#pragma unroll
    for (int i = 0; i < 2; ++i) rmax[i][0] = rmax[i][1] = NEG_INF;

    for (int c = 0; c < NCH; ++c) {
        if (c + 1 < NCH) {
            load_tile_async(sBbuf[(c + 1) & 1], Xg + (size_t)(c + 1) * NC * D, tid);
            cp_commit();
        }

        const uint32_t aB = aBbuf[c & 1];
        float acc[2][4][4];
#pragma unroll
        for (int mt = 0; mt < 2; ++mt)
#pragma unroll
            for (int nt = 0; nt < 4; ++nt)
#pragma unroll
                for (int q = 0; q < 4; ++q) acc[mt][nt][q] = 0.0f;

#pragma unroll 4
        for (int ks = 0; ks < KSTEPS; ++ks) {
            const uint32_t koff = (uint32_t)(ks * 16 * 2);
            uint32_t a[2][4];
#pragma unroll
            for (int mt = 0; mt < 2; ++mt)
                ldsm_x4(a[mt][0], a[mt][1], a[mt][2], a[mt][3],
                        aA + (uint32_t)(mt * 16 * STRIDE * 2) + koff);
            uint32_t bfr[4][2];
#pragma unroll
            for (int p = 0; p < 2; ++p) {
                uint32_t r0, r1, r2, r3;
                ldsm_x4(r0, r1, r2, r3,
                        aB + (uint32_t)(p * 16 * STRIDE * 2) + koff);
                bfr[p * 2][0]     = r0; bfr[p * 2][1]     = r1;
                bfr[p * 2 + 1][0] = r2; bfr[p * 2 + 1][1] = r3;
            }
#pragma unroll
            for (int mt = 0; mt < 2; ++mt)
#pragma unroll
                for (int nt = 0; nt < 4; ++nt)
                    mma_bf16(acc[mt][nt][0], acc[mt][nt][1],
                             acc[mt][nt][2], acc[mt][nt][3],
                             a[mt][0], a[mt][1], a[mt][2], a[mt][3],
                             bfr[nt][0], bfr[nt][1]);
        }

#pragma unroll
        for (int nt = 0; nt < 4; ++nt) {
            const int n0 = c * NC + warp_n * 32 + nt * 8 + (lane & 3) * 2;
            const float i0 = s_ina[n0], i1 = s_ina[n0 + 1];
#pragma unroll
            for (int mt = 0; mt < 2; ++mt) {
                rmax[mt][0] = fmaxf(rmax[mt][0],
                                    fmaxf(acc[mt][nt][0] * i0, acc[mt][nt][1] * i1));
                rmax[mt][1] = fmaxf(rmax[mt][1],
                                    fmaxf(acc[mt][nt][2] * i0, acc[mt][nt][3] * i1));
            }
        }

        if (c + 1 < NCH) {
            cp_wait0();
            __syncthreads();
        }
    }

#pragma unroll
    for (int mt = 0; mt < 2; ++mt)
#pragma unroll
        for (int rh = 0; rh < 2; ++rh) {
            float v = rmax[mt][rh];
            v = fmaxf(v, __shfl_xor_sync(0xffffffffu, v, 1));
            v = fmaxf(v, __shfl_xor_sync(0xffffffffu, v, 2));
            rmax[mt][rh] = v;
        }
    __syncthreads();
    if ((lane & 3) == 0) {
#pragma unroll
        for (int mt = 0; mt < 2; ++mt)
#pragma unroll
            for (int rh = 0; rh < 2; ++rh) {
                const int m = warp_m * 32 + mt * 16 + rh * 8 + (lane >> 2);
                red[warp_n * MT + m] = rmax[mt][rh];
            }
    }
    __syncthreads();
    if (tid < MT) {
        float v = fmaxf(fmaxf(red[tid], red[MT + tid]),
                        fmaxf(red[2 * MT + tid], red[3 * MT + tid]));
        g_simmax[b * SM_ + m0 + tid] = v * s_inb[tid];
    }

    // ---- last CTA of this batch runs the approximate top-16 ----
    __syncthreads();
    if (tid == 0) {
        __threadfence();
        s_old = atomicAdd(&g_done1[b], 1);
    }
    __syncthreads();
    if (s_old != (SM_ / MT) - 1) return;
    __threadfence();

    float e[8];
#pragma unroll
    for (int j = 0; j < 8; ++j) e[j] = g_simmax[b * SM_ + tid * 8 + j];

    for (int k = 0; k < NCAND; ++k) {
        float bv = e[0];
        int   bi = tid * 8;
#pragma unroll
        for (int j = 1; j < 8; ++j)
            if (e[j] > bv) { bv = e[j]; bi = tid * 8 + j; }
#pragma unroll
        for (int off = 16; off; off >>= 1) {
            float ov = __shfl_xor_sync(0xffffffffu, bv, off);
            int   oi = __shfl_xor_sync(0xffffffffu, bi, off);
            if (ov > bv || (ov == bv && oi < bi)) { bv = ov; bi = oi; }
        }
        if (lane == 0) { swv[wid] = bv; swi[wid] = bi; }
        __syncthreads();
        if (wid == 0) {
            float fv = (lane < 16) ? swv[lane] : NEG_INF;
            int   fi = (lane < 16) ? swi[lane] : 0x7fffffff;
#pragma unroll
            for (int off = 8; off; off >>= 1) {
                float ov = __shfl_xor_sync(0xffffffffu, fv, off);
                int   oi = __shfl_xor_sync(0xffffffffu, fi, off);
                if (ov > fv || (ov == fv && oi < fi)) { fv = ov; fi = oi; }
            }
            if (lane == 0) {
                s_win = fi;
                g_cand[b * NCAND + k] = fi;
            }
        }
        __syncthreads();
        const int w = s_win;
        if ((w >> 3) == tid) e[w & 7] = NEG_INF;
    }
}

// ---------------------------------------------------------------------------
// 3) exact fp32 scores for candidate PAIRS, grid (B, 8); last CTA per batch
//    does the final top-5 selection + gather.
//    out layout (float32): 5 blocks of [B,D] then [B,TOPK] indices
// ---------------------------------------------------------------------------
__global__ __launch_bounds__(512)
void rerank_kernel(const float* __restrict__ x, const float* __restrict__ mem,
                   float* __restrict__ out) {
    __shared__ float s_wmax[16][2];
    __shared__ float s_invnb[2];
    __shared__ int   s_old;
    __shared__ int   s_sel[TOPK];

    const int b    = blockIdx.x;
    const int c0   = blockIdx.y * 2;
    const int tid  = threadIdx.x;
    const int wid  = tid >> 5;
    const int lane = tid & 31;

    const int i0 = g_cand[b * NCAND + c0];
    const int i1 = g_cand[b * NCAND + c0 + 1];
    const float4* M0 = reinterpret_cast<const float4*>(mem + ((size_t)b * SM_ + i0) * D);
    const float4* M1 = reinterpret_cast<const float4*>(mem + ((size_t)b * SM_ + i1) * D);
    const float4 m0a = M0[lane], m0b = M0[lane + 32];
    const float4 m1a = M1[lane], m1b = M1[lane + 32];

    if (wid < 2) {
        float s = wid ? dot8(m1a, m1b, m1a, m1b) : dot8(m0a, m0b, m0a, m0b);
#pragma unroll
        for (int off = 16; off; off >>= 1)
            s += __shfl_xor_sync(0xffffffffu, s, off);
        if (lane == 0) s_invnb[wid] = rsqrtf(s);
    }

    const float* Xb = x + (size_t)b * SX * D;
    float v0 = NEG_INF, v1 = NEG_INF;
#pragma unroll 2
    for (int i = 0; i < SX / 32; ++i) {     // 2 queries per warp per iteration
        const int sa = wid + 16 * (2 * i);
        const int sb = wid + 16 * (2 * i + 1);
        const float4* Xa = reinterpret_cast<const float4*>(Xb + (size_t)sa * D);
        const float4* Xc = reinterpret_cast<const float4*>(Xb + (size_t)sb * D);
        const float4 xa0 = Xa[lane], xa1 = Xa[lane + 32];
        const float4 xb0 = Xc[lane], xb1 = Xc[lane + 32];
        float d0 = dot8(m0a, m0b, xa0, xa1);
        float d1 = dot8(m1a, m1b, xa0, xa1);
        float d2 = dot8(m0a, m0b, xb0, xb1);
        float d3 = dot8(m1a, m1b, xb0, xb1);
#pragma unroll
        for (int off = 16; off; off >>= 1) {
            d0 += __shfl_xor_sync(0xffffffffu, d0, off);
            d1 += __shfl_xor_sync(0xffffffffu, d1, off);
            d2 += __shfl_xor_sync(0xffffffffu, d2, off);
            d3 += __shfl_xor_sync(0xffffffffu, d3, off);
        }
        const float ia = g_inv_na[b * SX + sa];
        const float ib = g_inv_na[b * SX + sb];
        v0 = fmaxf(v0, fmaxf(d0 * ia, d2 * ib));
        v1 = fmaxf(v1, fmaxf(d1 * ia, d3 * ib));
    }
    if (lane == 0) { s_wmax[wid][0] = v0; s_wmax[wid][1] = v1; }
    __syncthreads();
    if (tid < 2) {
        float m = NEG_INF;
#pragma unroll
        for (int j = 0; j < 16; ++j) m = fmaxf(m, s_wmax[j][tid]);
        g_score[b * NCAND + c0 + tid] = m * s_invnb[tid];
    }

    // ---- last CTA of this batch: select top-5 and gather ----
    __syncthreads();
    if (tid == 0) {
        __threadfence();
        s_old = atomicAdd(&g_done2[b], 1);
    }
    __syncthreads();
    if (s_old != NCAND / 2 - 1) return;
    __threadfence();

    if (tid == 0) {
        float sc[NCAND];
        int   ix[NCAND];
        for (int i = 0; i < NCAND; ++i) {
            sc[i] = g_score[b * NCAND + i];
            ix[i] = g_cand[b * NCAND + i];
        }
        for (int k = 0; k < TOPK; ++k) {
            int best = k;
            for (int j = k + 1; j < NCAND; ++j)
                if (sc[j] > sc[best] || (sc[j] == sc[best] && ix[j] < ix[best])) best = j;
            float ts = sc[k]; sc[k] = sc[best]; sc[best] = ts;
            int   ti = ix[k]; ix[k] = ix[best]; ix[best] = ti;
            s_sel[k] = ix[k];
        }
    }
    __syncthreads();

    if (tid < D) {
#pragma unroll
        for (int k = 0; k < TOPK; ++k)
            out[(size_t)k * B * D + (size_t)b * D + tid] =
                mem[((size_t)b * SM_ + s_sel[k]) * D + tid];
    }
    if (tid < TOPK)
        out[(size_t)TOPK * B * D + b * TOPK + tid] = (float)s_sel[tid];
}

// ---------------------------------------------------------------------------
extern "C" void kernel_launch(void* const* d_in, const int* in_sizes, int n_in,
                              void* d_out, int out_size) {
    const float* x   = (const float*)d_in[0];   // [B, SX, D]
    const float* mem = (const float*)d_in[1];   // [B, SM, D]
    float* out = (float*)d_out;
    (void)in_sizes; (void)n_in; (void)out_size;

    invnorm_x_kernel<<<(B * SX) / 8, 256>>>(x);

    const int smem_bytes = (MT * STRIDE + 2 * NC * STRIDE) * 2
                         + (SX + MT + 4 * MT) * 4;               // ~208 KB dynamic
    static bool attr_set = false;   // idempotent attribute, not work caching
    if (!attr_set) {
        cudaFuncSetAttribute(simmax_mma_kernel,
                             cudaFuncAttributeMaxDynamicSharedMemorySize, smem_bytes);
        attr_set = true;
    }
    dim3 grid(SM_ / MT, B);
    simmax_mma_kernel<<<grid, NTHREADS, smem_bytes>>>(mem);

    rerank_kernel<<<dim3(B, NCAND / 2), 512>>>(x, mem, out);
}

// round 13
// speedup vs baseline: 1.0741x; 1.0741x over previous
#include <cuda_runtime.h>
#include <cuda_bf16.h>
#include <cstdint>

// Problem constants
#define B    32
#define SX   512
#define SM_  4096
#define D    256
#define TOPK 5
#define NCAND 16

#define NEG_INF (__int_as_float(0xff800000))

// GEMM tiling
#define MT   128          // mem rows per CTA
#define NC   128          // query chunk
#define NCH  (SX / NC)    // 4 chunks
#define KSTEPS (D / 16)   // 16 k-steps of 16
#define STRIDE 264        // bf16 elems per smem row (528B: 16B aligned, 4-bank stagger)
#define NTHREADS 512

// Scratch (no allocations allowed)
__device__ float g_inv_na[B * SX];
__device__ float g_simmax[B * SM_];
__device__ int   g_cand[B * NCAND];
__device__ float g_score[B * NCAND];
__device__ __nv_bfloat16 g_xbf[B * SX * D];    // 8 MB

// ---------------------------------------------------------------------------
// helpers
// ---------------------------------------------------------------------------
__device__ __forceinline__ uint32_t smem_u32(const void* p) {
    return (uint32_t)__cvta_generic_to_shared(p);
}

__device__ __forceinline__ uint32_t pack_bf2(float a, float b) {
    __nv_bfloat162 h = __float22bfloat162_rn(make_float2(a, b));
    return *reinterpret_cast<uint32_t*>(&h);
}

__device__ __forceinline__ void cp16(uint32_t dst, const void* src) {
    asm volatile("cp.async.cg.shared.global [%0], [%1], 16;" :: "r"(dst), "l"(src));
}
__device__ __forceinline__ void cp_commit() {
    asm volatile("cp.async.commit_group;" ::: "memory");
}
__device__ __forceinline__ void cp_wait0() {
    asm volatile("cp.async.wait_group 0;" ::: "memory");
}

__device__ __forceinline__ void ldsm_x4(uint32_t& r0, uint32_t& r1,
                                        uint32_t& r2, uint32_t& r3, uint32_t addr) {
    asm volatile("ldmatrix.sync.aligned.m8n8.x4.shared.b16 {%0,%1,%2,%3}, [%4];"
                 : "=r"(r0), "=r"(r1), "=r"(r2), "=r"(r3) : "r"(addr));
}

__device__ __forceinline__ void mma_bf16(float& c0, float& c1, float& c2, float& c3,
                                         uint32_t a0, uint32_t a1, uint32_t a2, uint32_t a3,
                                         uint32_t b0, uint32_t b1) {
    asm volatile(
        "mma.sync.aligned.m16n8k16.row.col.f32.bf16.bf16.f32 "
        "{%0,%1,%2,%3}, {%4,%5,%6,%7}, {%8,%9}, {%0,%1,%2,%3};"
        : "+f"(c0), "+f"(c1), "+f"(c2), "+f"(c3)
        : "r"(a0), "r"(a1), "r"(a2), "r"(a3), "r"(b0), "r"(b1));
}

__device__ __forceinline__ float dot8(const float4& a0, const float4& a1,
                                      const float4& b0, const float4& b1) {
    float s = a0.x * b0.x;
    s = fmaf(a0.y, b0.y, s);
    s = fmaf(a0.z, b0.z, s);
    s = fmaf(a0.w, b0.w, s);
    s = fmaf(a1.x, b1.x, s);
    s = fmaf(a1.y, b1.y, s);
    s = fmaf(a1.z, b1.z, s);
    s = fmaf(a1.w, b1.w, s);
    return s;
}

// ---------------------------------------------------------------------------
// 1) x only: inverse L2 norm per row + bf16 conversion (one warp per row)
// ---------------------------------------------------------------------------
__global__ void invnorm_x_kernel(const float* __restrict__ in) {
    int gwarp = (blockIdx.x * blockDim.x + threadIdx.x) >> 5;
    int lane  = threadIdx.x & 31;
    if (gwarp >= B * SX) return;
    const float4* r = reinterpret_cast<const float4*>(in + (size_t)gwarp * D);
    float4 v0 = r[lane];
    float4 v1 = r[lane + 32];

    __nv_bfloat16* dst = g_xbf + (size_t)gwarp * D;
    uint2 wa = make_uint2(pack_bf2(v0.x, v0.y), pack_bf2(v0.z, v0.w));
    uint2 wb = make_uint2(pack_bf2(v1.x, v1.y), pack_bf2(v1.z, v1.w));
    reinterpret_cast<uint64_t*>(dst)[lane]      = *reinterpret_cast<uint64_t*>(&wa);
    reinterpret_cast<uint64_t*>(dst)[lane + 32] = *reinterpret_cast<uint64_t*>(&wb);

    float s = v0.x * v0.x + v0.y * v0.y + v0.z * v0.z + v0.w * v0.w
            + v1.x * v1.x + v1.y * v1.y + v1.z * v1.z + v1.w * v1.w;
#pragma unroll
    for (int off = 16; off; off >>= 1)
        s += __shfl_xor_sync(0xffffffffu, s, off);
    if (lane == 0) g_inv_na[gwarp] = rsqrtf(s);
}

// ---------------------------------------------------------------------------
// 2) fused tensor sim-max (R10/R11 proven): A fp32->bf16 in prologue,
//    in-kernel row norms, mma.sync bf16, double-buffered cp.async B chunks.
// ---------------------------------------------------------------------------
__device__ __forceinline__ void load_tile_async(uint32_t sdst,
                                                const __nv_bfloat16* gsrc, int tid) {
#pragma unroll
    for (int i = tid; i < MT * 32; i += NTHREADS) {
        const int r = i >> 5, c = i & 31;
        cp16(sdst + (uint32_t)(r * (STRIDE * 2) + c * 16), gsrc + (size_t)r * D + c * 8);
    }
}

__global__ __launch_bounds__(NTHREADS, 1)
void simmax_mma_kernel(const float* __restrict__ mem) {
    extern __shared__ char smem[];
    __nv_bfloat16* sA  = reinterpret_cast<__nv_bfloat16*>(smem);   // [128][STRIDE]
    __nv_bfloat16* sB0 = sA + MT * STRIDE;
    __nv_bfloat16* sB1 = sB0 + NC * STRIDE;
    float* s_ina = reinterpret_cast<float*>(sB1 + NC * STRIDE);    // [512]
    float* s_inb = s_ina + SX;                                     // [128]
    float* red   = s_inb + MT;                                     // [4*128]

    const int tid    = threadIdx.x;
    const int wid    = tid >> 5;
    const int lane   = tid & 31;
    const int b      = blockIdx.y;
    const int m0     = blockIdx.x * MT;
    const int warp_m = wid & 3;
    const int warp_n = wid >> 2;

    const float* Ag = mem + ((size_t)b * SM_ + m0) * D;
    const __nv_bfloat16* Xg = g_xbf + (size_t)b * SX * D;

    load_tile_async(smem_u32(sB0), Xg, tid);
    cp_commit();

    // A tile: fp32 LDG -> bf16 STS. 128 rows x 64 float4 = 8192 ops.
#pragma unroll
    for (int j = 0; j < 16; ++j) {
        const int idx = j * NTHREADS + tid;
        const int r = idx >> 6, q = idx & 63;
        float4 v = reinterpret_cast<const float4*>(Ag)[(size_t)r * 64 + q];
        uint2 w = make_uint2(pack_bf2(v.x, v.y), pack_bf2(v.z, v.w));
        *reinterpret_cast<uint2*>(
            reinterpret_cast<char*>(sA) + r * (STRIDE * 2) + q * 8) = w;
    }
#pragma unroll
    for (int i = tid; i < SX; i += NTHREADS) s_ina[i] = g_inv_na[b * SX + i];
    __syncthreads();

    // per-row inv norms from the bf16 A tile: 4 threads per row
    {
        const int r  = tid >> 2;
        const int q0 = (tid & 3) * 64;
        const __nv_bfloat16* row = sA + r * STRIDE + q0;
        float s = 0.0f;
#pragma unroll
        for (int k = 0; k < 32; ++k) {
            float2 p = __bfloat1622float2(
                *reinterpret_cast<const __nv_bfloat162*>(row + 2 * k));
            s = fmaf(p.x, p.x, fmaf(p.y, p.y, s));
        }
        s += __shfl_xor_sync(0xffffffffu, s, 1);
        s += __shfl_xor_sync(0xffffffffu, s, 2);
        if ((tid & 3) == 0) s_inb[r] = rsqrtf(s);
    }
    cp_wait0();
    __syncthreads();

    const int g = lane >> 3, r8 = lane & 7;
    const uint32_t aA = smem_u32(sA) +
        (uint32_t)(((warp_m * 32 + (g & 1) * 8 + r8) * STRIDE + (g >> 1) * 8) * 2);
    const uint32_t aBoff =
        (uint32_t)(((warp_n * 32 + (g >> 1) * 8 + r8) * STRIDE + (g & 1) * 8) * 2);
    const uint32_t aBbuf[2] = { smem_u32(sB0) + aBoff, smem_u32(sB1) + aBoff };
    const uint32_t sBbuf[2] = { smem_u32(sB0), smem_u32(sB1) };

    float rmax[2][2];
#pragma unroll
    for (int i = 0; i < 2; ++i) rmax[i][0] = rmax[i][1] = NEG_INF;

    for (int c = 0; c < NCH; ++c) {
        if (c + 1 < NCH) {
            load_tile_async(sBbuf[(c + 1) & 1], Xg + (size_t)(c + 1) * NC * D, tid);
            cp_commit();
        }

        const uint32_t aB = aBbuf[c & 1];
        float acc[2][4][4];
#pragma unroll
        for (int mt = 0; mt < 2; ++mt)
#pragma unroll
            for (int nt = 0; nt < 4; ++nt)
#pragma unroll
                for (int q = 0; q < 4; ++q) acc[mt][nt][q] = 0.0f;

#pragma unroll 4
        for (int ks = 0; ks < KSTEPS; ++ks) {
            const uint32_t koff = (uint32_t)(ks * 16 * 2);
            uint32_t a[2][4];
#pragma unroll
            for (int mt = 0; mt < 2; ++mt)
                ldsm_x4(a[mt][0], a[mt][1], a[mt][2], a[mt][3],
                        aA + (uint32_t)(mt * 16 * STRIDE * 2) + koff);
            uint32_t bfr[4][2];
#pragma unroll
            for (int p = 0; p < 2; ++p) {
                uint32_t r0, r1, r2, r3;
                ldsm_x4(r0, r1, r2, r3,
                        aB + (uint32_t)(p * 16 * STRIDE * 2) + koff);
                bfr[p * 2][0]     = r0; bfr[p * 2][1]     = r1;
                bfr[p * 2 + 1][0] = r2; bfr[p * 2 + 1][1] = r3;
            }
#pragma unroll
            for (int mt = 0; mt < 2; ++mt)
#pragma unroll
                for (int nt = 0; nt < 4; ++nt)
                    mma_bf16(acc[mt][nt][0], acc[mt][nt][1],
                             acc[mt][nt][2], acc[mt][nt][3],
                             a[mt][0], a[mt][1], a[mt][2], a[mt][3],
                             bfr[nt][0], bfr[nt][1]);
        }

#pragma unroll
        for (int nt = 0; nt < 4; ++nt) {
            const int n0 = c * NC + warp_n * 32 + nt * 8 + (lane & 3) * 2;
            const float i0 = s_ina[n0], i1 = s_ina[n0 + 1];
#pragma unroll
            for (int mt = 0; mt < 2; ++mt) {
                rmax[mt][0] = fmaxf(rmax[mt][0],
                                    fmaxf(acc[mt][nt][0] * i0, acc[mt][nt][1] * i1));
                rmax[mt][1] = fmaxf(rmax[mt][1],
                                    fmaxf(acc[mt][nt][2] * i0, acc[mt][nt][3] * i1));
            }
        }

        if (c + 1 < NCH) {
            cp_wait0();
            __syncthreads();
        }
    }

#pragma unroll
    for (int mt = 0; mt < 2; ++mt)
#pragma unroll
        for (int rh = 0; rh < 2; ++rh) {
            float v = rmax[mt][rh];
            v = fmaxf(v, __shfl_xor_sync(0xffffffffu, v, 1));
            v = fmaxf(v, __shfl_xor_sync(0xffffffffu, v, 2));
            rmax[mt][rh] = v;
        }
    __syncthreads();
    if ((lane & 3) == 0) {
#pragma unroll
        for (int mt = 0; mt < 2; ++mt)
#pragma unroll
            for (int rh = 0; rh < 2; ++rh) {
                const int m = warp_m * 32 + mt * 16 + rh * 8 + (lane >> 2);
                red[warp_n * MT + m] = rmax[mt][rh];
            }
    }
    __syncthreads();
    if (tid < MT) {
        float v = fmaxf(fmaxf(red[tid], red[MT + tid]),
                        fmaxf(red[2 * MT + tid], red[3 * MT + tid]));
        g_simmax[b * SM_ + m0 + tid] = v * s_inb[tid];
    }
}

// ---------------------------------------------------------------------------
// 3) approx top-16 per batch: register-resident, warp-shuffle argmax rounds
// ---------------------------------------------------------------------------
__global__ __launch_bounds__(512)
void topk_approx_kernel() {
    __shared__ float swv[16];
    __shared__ int   swi[16];
    __shared__ int   s_win;

    const int b    = blockIdx.x;
    const int tid  = threadIdx.x;
    const int wid  = tid >> 5;
    const int lane = tid & 31;

    float e[8];
#pragma unroll
    for (int j = 0; j < 8; ++j) e[j] = g_simmax[b * SM_ + tid * 8 + j];

    for (int k = 0; k < NCAND; ++k) {
        float bv = e[0];
        int   bi = tid * 8;
#pragma unroll
        for (int j = 1; j < 8; ++j)
            if (e[j] > bv) { bv = e[j]; bi = tid * 8 + j; }
#pragma unroll
        for (int off = 16; off; off >>= 1) {
            float ov = __shfl_xor_sync(0xffffffffu, bv, off);
            int   oi = __shfl_xor_sync(0xffffffffu, bi, off);
            if (ov > bv || (ov == bv && oi < bi)) { bv = ov; bi = oi; }
        }
        if (lane == 0) { swv[wid] = bv; swi[wid] = bi; }
        __syncthreads();
        if (wid == 0) {
            float fv = (lane < 16) ? swv[lane] : NEG_INF;
            int   fi = (lane < 16) ? swi[lane] : 0x7fffffff;
#pragma unroll
            for (int off = 8; off; off >>= 1) {
                float ov = __shfl_xor_sync(0xffffffffu, fv, off);
                int   oi = __shfl_xor_sync(0xffffffffu, fi, off);
                if (ov > fv || (ov == fv && oi < fi)) { fv = ov; fi = oi; }
            }
            if (lane == 0) {
                s_win = fi;
                g_cand[b * NCAND + k] = fi;
            }
        }
        __syncthreads();
        const int w = s_win;
        if ((w >> 3) == tid) e[w & 7] = NEG_INF;
    }
}

// ---------------------------------------------------------------------------
// 4) exact fp32 scores for candidate PAIRS: grid (B, 8), 512 threads.
//    ILP x2: each warp scores 2 queries per iteration (4 indep dot chains).
// ---------------------------------------------------------------------------
__global__ __launch_bounds__(512)
void rerank_score_kernel(const float* __restrict__ x, const float* __restrict__ mem) {
    __shared__ float s_wmax[16][2];
    __shared__ float s_invnb[2];

    const int b    = blockIdx.x;
    const int c0   = blockIdx.y * 2;
    const int tid  = threadIdx.x;
    const int wid  = tid >> 5;
    const int lane = tid & 31;

    const int i0 = g_cand[b * NCAND + c0];
    const int i1 = g_cand[b * NCAND + c0 + 1];
    const float4* M0 = reinterpret_cast<const float4*>(mem + ((size_t)b * SM_ + i0) * D);
    const float4* M1 = reinterpret_cast<const float4*>(mem + ((size_t)b * SM_ + i1) * D);
    const float4 m0a = M0[lane], m0b = M0[lane + 32];
    const float4 m1a = M1[lane], m1b = M1[lane + 32];

    // exact fp32 inverse norms (warps 0 and 1)
    if (wid < 2) {
        float s = wid ? dot8(m1a, m1b, m1a, m1b) : dot8(m0a, m0b, m0a, m0b);
#pragma unroll
        for (int off = 16; off; off >>= 1)
            s += __shfl_xor_sync(0xffffffffu, s, off);
        if (lane == 0) s_invnb[wid] = rsqrtf(s);
    }

    const float* Xb = x + (size_t)b * SX * D;
    float v0 = NEG_INF, v1 = NEG_INF;
#pragma unroll 2
    for (int i = 0; i < SX / 32; ++i) {     // 2 queries per warp per iteration
        const int sa = wid + 16 * (2 * i);
        const int sb = wid + 16 * (2 * i + 1);
        const float4* Xa = reinterpret_cast<const float4*>(Xb + (size_t)sa * D);
        const float4* Xc = reinterpret_cast<const float4*>(Xb + (size_t)sb * D);
        const float4 xa0 = Xa[lane], xa1 = Xa[lane + 32];
        const float4 xb0 = Xc[lane], xb1 = Xc[lane + 32];
        float d0 = dot8(m0a, m0b, xa0, xa1);
        float d1 = dot8(m1a, m1b, xa0, xa1);
        float d2 = dot8(m0a, m0b, xb0, xb1);
        float d3 = dot8(m1a, m1b, xb0, xb1);
#pragma unroll
        for (int off = 16; off; off >>= 1) {
            d0 += __shfl_xor_sync(0xffffffffu, d0, off);
            d1 += __shfl_xor_sync(0xffffffffu, d1, off);
            d2 += __shfl_xor_sync(0xffffffffu, d2, off);
            d3 += __shfl_xor_sync(0xffffffffu, d3, off);
        }
        const float ia = g_inv_na[b * SX + sa];
        const float ib = g_inv_na[b * SX + sb];
        v0 = fmaxf(v0, fmaxf(d0 * ia, d2 * ib));
        v1 = fmaxf(v1, fmaxf(d1 * ia, d3 * ib));
    }
    if (lane == 0) { s_wmax[wid][0] = v0; s_wmax[wid][1] = v1; }
    __syncthreads();
    if (tid < 2) {
        float m = NEG_INF;
#pragma unroll
        for (int j = 0; j < 16; ++j) m = fmaxf(m, s_wmax[j][tid]);
        g_score[b * NCAND + c0 + tid] = m * s_invnb[tid];
    }
}

// ---------------------------------------------------------------------------
// 5) pick top-5 of the 16 exact scores, gather rows + indices.
//    out layout (float32): 5 blocks of [B,D] then [B,TOPK] indices
// ---------------------------------------------------------------------------
__global__ __launch_bounds__(256)
void select_gather_kernel(const float* __restrict__ mem, float* __restrict__ out) {
    __shared__ int s_sel[TOPK];
    const int b   = blockIdx.x;
    const int tid = threadIdx.x;

    if (tid == 0) {
        float sc[NCAND];
        int   ix[NCAND];
        for (int i = 0; i < NCAND; ++i) {
            sc[i] = g_score[b * NCAND + i];
            ix[i] = g_cand[b * NCAND + i];
        }
        for (int k = 0; k < TOPK; ++k) {
            int best = k;
            for (int j = k + 1; j < NCAND; ++j)
                if (sc[j] > sc[best] || (sc[j] == sc[best] && ix[j] < ix[best])) best = j;
            float ts = sc[k]; sc[k] = sc[best]; sc[best] = ts;
            int   ti = ix[k]; ix[k] = ix[best]; ix[best] = ti;
            s_sel[k] = ix[k];
        }
    }
    __syncthreads();

#pragma unroll
    for (int k = 0; k < TOPK; ++k)
        out[(size_t)k * B * D + (size_t)b * D + tid] =
            mem[((size_t)b * SM_ + s_sel[k]) * D + tid];
    if (tid < TOPK)
        out[(size_t)TOPK * B * D + b * TOPK + tid] = (float)s_sel[tid];
}

// ---------------------------------------------------------------------------
extern "C" void kernel_launch(void* const* d_in, const int* in_sizes, int n_in,
                              void* d_out, int out_size) {
    const float* x   = (const float*)d_in[0];   // [B, SX, D]
    const float* mem = (const float*)d_in[1];   // [B, SM, D]
    float* out = (float*)d_out;
    (void)in_sizes; (void)n_in; (void)out_size;

    invnorm_x_kernel<<<(B * SX) / 8, 256>>>(x);

    const int smem_bytes = (MT * STRIDE + 2 * NC * STRIDE) * 2
                         + (SX + MT + 4 * MT) * 4;               // ~208 KB dynamic
    static bool attr_set = false;   // idempotent attribute, not work caching
    if (!attr_set) {
        cudaFuncSetAttribute(simmax_mma_kernel,
                             cudaFuncAttributeMaxDynamicSharedMemorySize, smem_bytes);
        attr_set = true;
    }
    dim3 grid(SM_ / MT, B);
    simmax_mma_kernel<<<grid, NTHREADS, smem_bytes>>>(mem);

    topk_approx_kernel<<<B, 512>>>();
    rerank_score_kernel<<<dim3(B, NCAND / 2), 512>>>(x, mem);
    select_gather_kernel<<<B, 256>>>(mem, out);
}

// round 14
// speedup vs baseline: 1.1276x; 1.0499x over previous
#include <cuda_runtime.h>
#include <cuda_bf16.h>
#include <cstdint>

// Problem constants
#define B    32
#define SX   512
#define SM_  4096
#define D    256
#define TOPK 5
#define NCAND 8

#define NEG_INF (__int_as_float(0xff800000))

// GEMM tiling
#define MT   128          // mem rows per CTA
#define NC   128          // query chunk
#define NCH  (SX / NC)    // 4 chunks
#define KSTEPS (D / 16)   // 16 k-steps of 16
#define STRIDE 264        // bf16 elems per smem row (528B: 16B aligned, 4-bank stagger)
#define NTHREADS 512

// Scratch (no allocations allowed)
__device__ float g_inv_na[B * SX];
__device__ float g_simmax[B * SM_];
__device__ int   g_cand[B * NCAND];
__device__ float g_score[B * NCAND];
__device__ __nv_bfloat16 g_xbf[B * SX * D];    // 8 MB

// ---------------------------------------------------------------------------
// helpers
// ---------------------------------------------------------------------------
__device__ __forceinline__ uint32_t smem_u32(const void* p) {
    return (uint32_t)__cvta_generic_to_shared(p);
}

__device__ __forceinline__ uint32_t pack_bf2(float a, float b) {
    __nv_bfloat162 h = __float22bfloat162_rn(make_float2(a, b));
    return *reinterpret_cast<uint32_t*>(&h);
}

__device__ __forceinline__ void cp16(uint32_t dst, const void* src) {
    asm volatile("cp.async.cg.shared.global [%0], [%1], 16;" :: "r"(dst), "l"(src));
}
__device__ __forceinline__ void cp_commit() {
    asm volatile("cp.async.commit_group;" ::: "memory");
}
__device__ __forceinline__ void cp_wait0() {
    asm volatile("cp.async.wait_group 0;" ::: "memory");
}

__device__ __forceinline__ void ldsm_x4(uint32_t& r0, uint32_t& r1,
                                        uint32_t& r2, uint32_t& r3, uint32_t addr) {
    asm volatile("ldmatrix.sync.aligned.m8n8.x4.shared.b16 {%0,%1,%2,%3}, [%4];"
                 : "=r"(r0), "=r"(r1), "=r"(r2), "=r"(r3) : "r"(addr));
}

__device__ __forceinline__ void mma_bf16(float& c0, float& c1, float& c2, float& c3,
                                         uint32_t a0, uint32_t a1, uint32_t a2, uint32_t a3,
                                         uint32_t b0, uint32_t b1) {
    asm volatile(
        "mma.sync.aligned.m16n8k16.row.col.f32.bf16.bf16.f32 "
        "{%0,%1,%2,%3}, {%4,%5,%6,%7}, {%8,%9}, {%0,%1,%2,%3};"
        : "+f"(c0), "+f"(c1), "+f"(c2), "+f"(c3)
        : "r"(a0), "r"(a1), "r"(a2), "r"(a3), "r"(b0), "r"(b1));
}

__device__ __forceinline__ float dot8(const float4& a0, const float4& a1,
                                      const float4& b0, const float4& b1) {
    float s = a0.x * b0.x;
    s = fmaf(a0.y, b0.y, s);
    s = fmaf(a0.z, b0.z, s);
    s = fmaf(a0.w, b0.w, s);
    s = fmaf(a1.x, b1.x, s);
    s = fmaf(a1.y, b1.y, s);
    s = fmaf(a1.z, b1.z, s);
    s = fmaf(a1.w, b1.w, s);
    return s;
}

// ---------------------------------------------------------------------------
// 1) x only: inverse L2 norm per row + bf16 conversion (one warp per row)
// ---------------------------------------------------------------------------
__global__ void invnorm_x_kernel(const float* __restrict__ in) {
    int gwarp = (blockIdx.x * blockDim.x + threadIdx.x) >> 5;
    int lane  = threadIdx.x & 31;
    if (gwarp >= B * SX) return;
    const float4* r = reinterpret_cast<const float4*>(in + (size_t)gwarp * D);
    float4 v0 = r[lane];
    float4 v1 = r[lane + 32];

    __nv_bfloat16* dst = g_xbf + (size_t)gwarp * D;
    uint2 wa = make_uint2(pack_bf2(v0.x, v0.y), pack_bf2(v0.z, v0.w));
    uint2 wb = make_uint2(pack_bf2(v1.x, v1.y), pack_bf2(v1.z, v1.w));
    reinterpret_cast<uint64_t*>(dst)[lane]      = *reinterpret_cast<uint64_t*>(&wa);
    reinterpret_cast<uint64_t*>(dst)[lane + 32] = *reinterpret_cast<uint64_t*>(&wb);

    float s = v0.x * v0.x + v0.y * v0.y + v0.z * v0.z + v0.w * v0.w
            + v1.x * v1.x + v1.y * v1.y + v1.z * v1.z + v1.w * v1.w;
#pragma unroll
    for (int off = 16; off; off >>= 1)
        s += __shfl_xor_sync(0xffffffffu, s, off);
    if (lane == 0) g_inv_na[gwarp] = rsqrtf(s);
}

// ---------------------------------------------------------------------------
// 2) fused tensor sim-max (R10/R11 proven): A fp32->bf16 in prologue,
//    in-kernel row norms, mma.sync bf16, double-buffered cp.async B chunks.
// ---------------------------------------------------------------------------
__device__ __forceinline__ void load_tile_async(uint32_t sdst,
                                                const __nv_bfloat16* gsrc, int tid) {
#pragma unroll
    for (int i = tid; i < MT * 32; i += NTHREADS) {
        const int r = i >> 5, c = i & 31;
        cp16(sdst + (uint32_t)(r * (STRIDE * 2) + c * 16), gsrc + (size_t)r * D + c * 8);
    }
}

__global__ __launch_bounds__(NTHREADS, 1)
void simmax_mma_kernel(const float* __restrict__ mem) {
    extern __shared__ char smem[];
    __nv_bfloat16* sA  = reinterpret_cast<__nv_bfloat16*>(smem);   // [128][STRIDE]
    __nv_bfloat16* sB0 = sA + MT * STRIDE;
    __nv_bfloat16* sB1 = sB0 + NC * STRIDE;
    float* s_ina = reinterpret_cast<float*>(sB1 + NC * STRIDE);    // [512]
    float* s_inb = s_ina + SX;                                     // [128]
    float* red   = s_inb + MT;                                     // [4*128]

    const int tid    = threadIdx.x;
    const int wid    = tid >> 5;
    const int lane   = tid & 31;
    const int b      = blockIdx.y;
    const int m0     = blockIdx.x * MT;
    const int warp_m = wid & 3;
    const int warp_n = wid >> 2;

    const float* Ag = mem + ((size_t)b * SM_ + m0) * D;
    const __nv_bfloat16* Xg = g_xbf + (size_t)b * SX * D;

    load_tile_async(smem_u32(sB0), Xg, tid);
    cp_commit();

    // A tile: fp32 LDG -> bf16 STS. 128 rows x 64 float4 = 8192 ops.
#pragma unroll
    for (int j = 0; j < 16; ++j) {
        const int idx = j * NTHREADS + tid;
        const int r = idx >> 6, q = idx & 63;
        float4 v = reinterpret_cast<const float4*>(Ag)[(size_t)r * 64 + q];
        uint2 w = make_uint2(pack_bf2(v.x, v.y), pack_bf2(v.z, v.w));
        *reinterpret_cast<uint2*>(
            reinterpret_cast<char*>(sA) + r * (STRIDE * 2) + q * 8) = w;
    }
#pragma unroll
    for (int i = tid; i < SX; i += NTHREADS) s_ina[i] = g_inv_na[b * SX + i];
    __syncthreads();

    // per-row inv norms from the bf16 A tile: 4 threads per row
    {
        const int r  = tid >> 2;
        const int q0 = (tid & 3) * 64;
        const __nv_bfloat16* row = sA + r * STRIDE + q0;
        float s = 0.0f;
#pragma unroll
        for (int k = 0; k < 32; ++k) {
            float2 p = __bfloat1622float2(
                *reinterpret_cast<const __nv_bfloat162*>(row + 2 * k));
            s = fmaf(p.x, p.x, fmaf(p.y, p.y, s));
        }
        s += __shfl_xor_sync(0xffffffffu, s, 1);
        s += __shfl_xor_sync(0xffffffffu, s, 2);
        if ((tid & 3) == 0) s_inb[r] = rsqrtf(s);
    }
    cp_wait0();
    __syncthreads();

    const int g = lane >> 3, r8 = lane & 7;
    const uint32_t aA = smem_u32(sA) +
        (uint32_t)(((warp_m * 32 + (g & 1) * 8 + r8) * STRIDE + (g >> 1) * 8) * 2);
    const uint32_t aBoff =
        (uint32_t)(((warp_n * 32 + (g >> 1) * 8 + r8) * STRIDE + (g & 1) * 8) * 2);
    const uint32_t aBbuf[2] = { smem_u32(sB0) + aBoff, smem_u32(sB1) + aBoff };
    const uint32_t sBbuf[2] = { smem_u32(sB0), smem_u32(sB1) };

    float rmax[2][2];
#pragma unroll
    for (int i = 0; i < 2; ++i) rmax[i][0] = rmax[i][1] = NEG_INF;

    for (int c = 0; c < NCH; ++c) {
        if (c + 1 < NCH) {
            load_tile_async(sBbuf[(c + 1) & 1], Xg + (size_t)(c + 1) * NC * D, tid);
            cp_commit();
        }

        const uint32_t aB = aBbuf[c & 1];
        float acc[2][4][4];
#pragma unroll
        for (int mt = 0; mt < 2; ++mt)
#pragma unroll
            for (int nt = 0; nt < 4; ++nt)
#pragma unroll
                for (int q = 0; q < 4; ++q) acc[mt][nt][q] = 0.0f;

#pragma unroll 4
        for (int ks = 0; ks < KSTEPS; ++ks) {
            const uint32_t koff = (uint32_t)(ks * 16 * 2);
            uint32_t a[2][4];
#pragma unroll
            for (int mt = 0; mt < 2; ++mt)
                ldsm_x4(a[mt][0], a[mt][1], a[mt][2], a[mt][3],
                        aA + (uint32_t)(mt * 16 * STRIDE * 2) + koff);
            uint32_t bfr[4][2];
#pragma unroll
            for (int p = 0; p < 2; ++p) {
                uint32_t r0, r1, r2, r3;
                ldsm_x4(r0, r1, r2, r3,
                        aB + (uint32_t)(p * 16 * STRIDE * 2) + koff);
                bfr[p * 2][0]     = r0; bfr[p * 2][1]     = r1;
                bfr[p * 2 + 1][0] = r2; bfr[p * 2 + 1][1] = r3;
            }
#pragma unroll
            for (int mt = 0; mt < 2; ++mt)
#pragma unroll
                for (int nt = 0; nt < 4; ++nt)
                    mma_bf16(acc[mt][nt][0], acc[mt][nt][1],
                             acc[mt][nt][2], acc[mt][nt][3],
                             a[mt][0], a[mt][1], a[mt][2], a[mt][3],
                             bfr[nt][0], bfr[nt][1]);
        }

#pragma unroll
        for (int nt = 0; nt < 4; ++nt) {
            const int n0 = c * NC + warp_n * 32 + nt * 8 + (lane & 3) * 2;
            const float i0 = s_ina[n0], i1 = s_ina[n0 + 1];
#pragma unroll
            for (int mt = 0; mt < 2; ++mt) {
                rmax[mt][0] = fmaxf(rmax[mt][0],
                                    fmaxf(acc[mt][nt][0] * i0, acc[mt][nt][1] * i1));
                rmax[mt][1] = fmaxf(rmax[mt][1],
                                    fmaxf(acc[mt][nt][2] * i0, acc[mt][nt][3] * i1));
            }
        }

        if (c + 1 < NCH) {
            cp_wait0();
            __syncthreads();
        }
    }

#pragma unroll
    for (int mt = 0; mt < 2; ++mt)
#pragma unroll
        for (int rh = 0; rh < 2; ++rh) {
            float v = rmax[mt][rh];
            v = fmaxf(v, __shfl_xor_sync(0xffffffffu, v, 1));
            v = fmaxf(v, __shfl_xor_sync(0xffffffffu, v, 2));
            rmax[mt][rh] = v;
        }
    __syncthreads();
    if ((lane & 3) == 0) {
#pragma unroll
        for (int mt = 0; mt < 2; ++mt)
#pragma unroll
            for (int rh = 0; rh < 2; ++rh) {
                const int m = warp_m * 32 + mt * 16 + rh * 8 + (lane >> 2);
                red[warp_n * MT + m] = rmax[mt][rh];
            }
    }
    __syncthreads();
    if (tid < MT) {
        float v = fmaxf(fmaxf(red[tid], red[MT + tid]),
                        fmaxf(red[2 * MT + tid], red[3 * MT + tid]));
        g_simmax[b * SM_ + m0 + tid] = v * s_inb[tid];
    }
}

// ---------------------------------------------------------------------------
// 3) approx top-8 per batch: register-resident, warp-shuffle argmax rounds
// ---------------------------------------------------------------------------
__global__ __launch_bounds__(512)
void topk_approx_kernel() {
    __shared__ float swv[16];
    __shared__ int   swi[16];
    __shared__ int   s_win;

    const int b    = blockIdx.x;
    const int tid  = threadIdx.x;
    const int wid  = tid >> 5;
    const int lane = tid & 31;

    float e[8];
#pragma unroll
    for (int j = 0; j < 8; ++j) e[j] = g_simmax[b * SM_ + tid * 8 + j];

    for (int k = 0; k < NCAND; ++k) {
        float bv = e[0];
        int   bi = tid * 8;
#pragma unroll
        for (int j = 1; j < 8; ++j)
            if (e[j] > bv) { bv = e[j]; bi = tid * 8 + j; }
#pragma unroll
        for (int off = 16; off; off >>= 1) {
            float ov = __shfl_xor_sync(0xffffffffu, bv, off);
            int   oi = __shfl_xor_sync(0xffffffffu, bi, off);
            if (ov > bv || (ov == bv && oi < bi)) { bv = ov; bi = oi; }
        }
        if (lane == 0) { swv[wid] = bv; swi[wid] = bi; }
        __syncthreads();
        if (wid == 0) {
            float fv = (lane < 16) ? swv[lane] : NEG_INF;
            int   fi = (lane < 16) ? swi[lane] : 0x7fffffff;
#pragma unroll
            for (int off = 8; off; off >>= 1) {
                float ov = __shfl_xor_sync(0xffffffffu, fv, off);
                int   oi = __shfl_xor_sync(0xffffffffu, fi, off);
                if (ov > fv || (ov == fv && oi < fi)) { fv = ov; fi = oi; }
            }
            if (lane == 0) {
                s_win = fi;
                g_cand[b * NCAND + k] = fi;
            }
        }
        __syncthreads();
        const int w = s_win;
        if ((w >> 3) == tid) e[w & 7] = NEG_INF;
    }
}

// ---------------------------------------------------------------------------
// 4) exact fp32 scores for candidate PAIRS: grid (B, 4), 512 threads.
//    Candidate rows in registers; each warp owns 32 queries; butterfly dots.
// ---------------------------------------------------------------------------
__global__ __launch_bounds__(512)
void rerank_score_kernel(const float* __restrict__ x, const float* __restrict__ mem) {
    __shared__ float s_wmax[16][2];
    __shared__ float s_invnb[2];

    const int b    = blockIdx.x;
    const int c0   = blockIdx.y * 2;
    const int tid  = threadIdx.x;
    const int wid  = tid >> 5;
    const int lane = tid & 31;

    const int i0 = g_cand[b * NCAND + c0];
    const int i1 = g_cand[b * NCAND + c0 + 1];
    const float4* M0 = reinterpret_cast<const float4*>(mem + ((size_t)b * SM_ + i0) * D);
    const float4* M1 = reinterpret_cast<const float4*>(mem + ((size_t)b * SM_ + i1) * D);
    const float4 m0a = M0[lane], m0b = M0[lane + 32];
    const float4 m1a = M1[lane], m1b = M1[lane + 32];

    // exact fp32 inverse norms (warps 0 and 1)
    if (wid < 2) {
        float s = wid ? dot8(m1a, m1b, m1a, m1b) : dot8(m0a, m0b, m0a, m0b);
#pragma unroll
        for (int off = 16; off; off >>= 1)
            s += __shfl_xor_sync(0xffffffffu, s, off);
        if (lane == 0) s_invnb[wid] = rsqrtf(s);
    }

    const float* Xb = x + (size_t)b * SX * D;
    float v0 = NEG_INF, v1 = NEG_INF;
#pragma unroll 4
    for (int i = 0; i < SX / 16; ++i) {
        const int s = wid + 16 * i;
        const float4* X = reinterpret_cast<const float4*>(Xb + (size_t)s * D);
        const float4 xa = X[lane], xb = X[lane + 32];
        float d0 = dot8(m0a, m0b, xa, xb);
        float d1 = dot8(m1a, m1b, xa, xb);
#pragma unroll
        for (int off = 16; off; off >>= 1) {
            d0 += __shfl_xor_sync(0xffffffffu, d0, off);
            d1 += __shfl_xor_sync(0xffffffffu, d1, off);
        }
        const float ina = g_inv_na[b * SX + s];
        v0 = fmaxf(v0, d0 * ina);
        v1 = fmaxf(v1, d1 * ina);
    }
    if (lane == 0) { s_wmax[wid][0] = v0; s_wmax[wid][1] = v1; }
    __syncthreads();
    if (tid < 2) {
        float m = NEG_INF;
#pragma unroll
        for (int j = 0; j < 16; ++j) m = fmaxf(m, s_wmax[j][tid]);
        g_score[b * NCAND + c0 + tid] = m * s_invnb[tid];
    }
}

// ---------------------------------------------------------------------------
// 5) pick top-5 of the 8 exact scores, gather rows + indices.
//    out layout (float32): 5 blocks of [B,D] then [B,TOPK] indices
// ---------------------------------------------------------------------------
__global__ __launch_bounds__(256)
void select_gather_kernel(const float* __restrict__ mem, float* __restrict__ out) {
    __shared__ int s_sel[TOPK];
    const int b   = blockIdx.x;
    const int tid = threadIdx.x;

    if (tid == 0) {
        float sc[NCAND];
        int   ix[NCAND];
        for (int i = 0; i < NCAND; ++i) {
            sc[i] = g_score[b * NCAND + i];
            ix[i] = g_cand[b * NCAND + i];
        }
        for (int k = 0; k < TOPK; ++k) {
            int best = k;
            for (int j = k + 1; j < NCAND; ++j)
                if (sc[j] > sc[best] || (sc[j] == sc[best] && ix[j] < ix[best])) best = j;
            float ts = sc[k]; sc[k] = sc[best]; sc[best] = ts;
            int   ti = ix[k]; ix[k] = ix[best]; ix[best] = ti;
            s_sel[k] = ix[k];
        }
    }
    __syncthreads();

#pragma unroll
    for (int k = 0; k < TOPK; ++k)
        out[(size_t)k * B * D + (size_t)b * D + tid] =
            mem[((size_t)b * SM_ + s_sel[k]) * D + tid];
    if (tid < TOPK)
        out[(size_t)TOPK * B * D + b * TOPK + tid] = (float)s_sel[tid];
}

// ---------------------------------------------------------------------------
extern "C" void kernel_launch(void* const* d_in, const int* in_sizes, int n_in,
                              void* d_out, int out_size) {
    const float* x   = (const float*)d_in[0];   // [B, SX, D]
    const float* mem = (const float*)d_in[1];   // [B, SM, D]
    float* out = (float*)d_out;
    (void)in_sizes; (void)n_in; (void)out_size;

    invnorm_x_kernel<<<(B * SX) / 8, 256>>>(x);

    const int smem_bytes = (MT * STRIDE + 2 * NC * STRIDE) * 2
                         + (SX + MT + 4 * MT) * 4;               // ~208 KB dynamic
    static bool attr_set = false;   // idempotent attribute, not work caching
    if (!attr_set) {
        cudaFuncSetAttribute(simmax_mma_kernel,
                             cudaFuncAttributeMaxDynamicSharedMemorySize, smem_bytes);
        attr_set = true;
    }
    dim3 grid(SM_ / MT, B);
    simmax_mma_kernel<<<grid, NTHREADS, smem_bytes>>>(mem);

    topk_approx_kernel<<<B, 512>>>();
    rerank_score_kernel<<<dim3(B, NCAND / 2), 512>>>(x, mem);
    select_gather_kernel<<<B, 256>>>(mem, out);
}

// round 15
// speedup vs baseline: 1.1626x; 1.0310x over previous
#include <cuda_runtime.h>
#include <cuda_bf16.h>
#include <cstdint>

// Problem constants
#define B    32
#define SX   512
#define SM_  4096
#define D    256
#define TOPK 5
#define NCAND 8
#define NSLICE 8          // stage-1 slices per batch (512 rows each)

#define NEG_INF (__int_as_float(0xff800000))

// GEMM tiling
#define MT   128
#define NC   128
#define NCH  (SX / NC)
#define KSTEPS (D / 16)
#define STRIDE 264
#define NTHREADS 512

// Scratch (no allocations allowed)
__device__ float g_inv_na[B * SX];
__device__ float g_simmax[B * SM_];
__device__ float g_c1v[B * NSLICE * NCAND];   // stage-1 local top-8 values
__device__ int   g_c1i[B * NSLICE * NCAND];   // stage-1 local top-8 indices
__device__ float g_score2[B * NCAND * 2];     // per-half exact partial scores
__device__ int   g_candf[B * NCAND];          // final candidate indices (ordered list)
__device__ __nv_bfloat16 g_xbf[B * SX * D];   // 8 MB

// ---------------------------------------------------------------------------
// helpers
// ---------------------------------------------------------------------------
__device__ __forceinline__ uint32_t smem_u32(const void* p) {
    return (uint32_t)__cvta_generic_to_shared(p);
}

__device__ __forceinline__ uint32_t pack_bf2(float a, float b) {
    __nv_bfloat162 h = __float22bfloat162_rn(make_float2(a, b));
    return *reinterpret_cast<uint32_t*>(&h);
}

__device__ __forceinline__ void cp16(uint32_t dst, const void* src) {
    asm volatile("cp.async.cg.shared.global [%0], [%1], 16;" :: "r"(dst), "l"(src));
}
__device__ __forceinline__ void cp_commit() {
    asm volatile("cp.async.commit_group;" ::: "memory");
}
__device__ __forceinline__ void cp_wait0() {
    asm volatile("cp.async.wait_group 0;" ::: "memory");
}

__device__ __forceinline__ void ldsm_x4(uint32_t& r0, uint32_t& r1,
                                        uint32_t& r2, uint32_t& r3, uint32_t addr) {
    asm volatile("ldmatrix.sync.aligned.m8n8.x4.shared.b16 {%0,%1,%2,%3}, [%4];"
                 : "=r"(r0), "=r"(r1), "=r"(r2), "=r"(r3) : "r"(addr));
}

__device__ __forceinline__ void mma_bf16(float& c0, float& c1, float& c2, float& c3,
                                         uint32_t a0, uint32_t a1, uint32_t a2, uint32_t a3,
                                         uint32_t b0, uint32_t b1) {
    asm volatile(
        "mma.sync.aligned.m16n8k16.row.col.f32.bf16.bf16.f32 "
        "{%0,%1,%2,%3}, {%4,%5,%6,%7}, {%8,%9}, {%0,%1,%2,%3};"
        : "+f"(c0), "+f"(c1), "+f"(c2), "+f"(c3)
        : "r"(a0), "r"(a1), "r"(a2), "r"(a3), "r"(b0), "r"(b1));
}

__device__ __forceinline__ float dot8(const float4& a0, const float4& a1,
                                      const float4& b0, const float4& b1) {
    float s = a0.x * b0.x;
    s = fmaf(a0.y, b0.y, s);
    s = fmaf(a0.z, b0.z, s);
    s = fmaf(a0.w, b0.w, s);
    s = fmaf(a1.x, b1.x, s);
    s = fmaf(a1.y, b1.y, s);
    s = fmaf(a1.z, b1.z, s);
    s = fmaf(a1.w, b1.w, s);
    return s;
}

// argmax butterfly step with lowest-index tie-break (all lanes converge)
__device__ __forceinline__ void amax_bfly(float& v, int& i) {
#pragma unroll
    for (int off = 16; off; off >>= 1) {
        float ov = __shfl_xor_sync(0xffffffffu, v, off);
        int   oi = __shfl_xor_sync(0xffffffffu, i, off);
        if (ov > v || (ov == v && oi < i)) { v = ov; i = oi; }
    }
}

// ---------------------------------------------------------------------------
// 1) x only: inverse L2 norm per row + bf16 conversion (one warp per row)
// ---------------------------------------------------------------------------
__global__ void invnorm_x_kernel(const float* __restrict__ in) {
    int gwarp = (blockIdx.x * blockDim.x + threadIdx.x) >> 5;
    int lane  = threadIdx.x & 31;
    if (gwarp >= B * SX) return;
    const float4* r = reinterpret_cast<const float4*>(in + (size_t)gwarp * D);
    float4 v0 = r[lane];
    float4 v1 = r[lane + 32];

    __nv_bfloat16* dst = g_xbf + (size_t)gwarp * D;
    uint2 wa = make_uint2(pack_bf2(v0.x, v0.y), pack_bf2(v0.z, v0.w));
    uint2 wb = make_uint2(pack_bf2(v1.x, v1.y), pack_bf2(v1.z, v1.w));
    reinterpret_cast<uint64_t*>(dst)[lane]      = *reinterpret_cast<uint64_t*>(&wa);
    reinterpret_cast<uint64_t*>(dst)[lane + 32] = *reinterpret_cast<uint64_t*>(&wb);

    float s = v0.x * v0.x + v0.y * v0.y + v0.z * v0.z + v0.w * v0.w
            + v1.x * v1.x + v1.y * v1.y + v1.z * v1.z + v1.w * v1.w;
#pragma unroll
    for (int off = 16; off; off >>= 1)
        s += __shfl_xor_sync(0xffffffffu, s, off);
    if (lane == 0) g_inv_na[gwarp] = rsqrtf(s);
}

// ---------------------------------------------------------------------------
// 2) fused tensor sim-max (proven R10-R14 body, unchanged)
// ---------------------------------------------------------------------------
__device__ __forceinline__ void load_tile_async(uint32_t sdst,
                                                const __nv_bfloat16* gsrc, int tid) {
#pragma unroll
    for (int i = tid; i < MT * 32; i += NTHREADS) {
        const int r = i >> 5, c = i & 31;
        cp16(sdst + (uint32_t)(r * (STRIDE * 2) + c * 16), gsrc + (size_t)r * D + c * 8);
    }
}

__global__ __launch_bounds__(NTHREADS, 1)
void simmax_mma_kernel(const float* __restrict__ mem) {
    extern __shared__ char smem[];
    __nv_bfloat16* sA  = reinterpret_cast<__nv_bfloat16*>(smem);
    __nv_bfloat16* sB0 = sA + MT * STRIDE;
    __nv_bfloat16* sB1 = sB0 + NC * STRIDE;
    float* s_ina = reinterpret_cast<float*>(sB1 + NC * STRIDE);
    float* s_inb = s_ina + SX;
    float* red   = s_inb + MT;

    const int tid    = threadIdx.x;
    const int wid    = tid >> 5;
    const int lane   = tid & 31;
    const int b      = blockIdx.y;
    const int m0     = blockIdx.x * MT;
    const int warp_m = wid & 3;
    const int warp_n = wid >> 2;

    const float* Ag = mem + ((size_t)b * SM_ + m0) * D;
    const __nv_bfloat16* Xg = g_xbf + (size_t)b * SX * D;

    load_tile_async(smem_u32(sB0), Xg, tid);
    cp_commit();

#pragma unroll
    for (int j = 0; j < 16; ++j) {
        const int idx = j * NTHREADS + tid;
        const int r = idx >> 6, q = idx & 63;
        float4 v = reinterpret_cast<const float4*>(Ag)[(size_t)r * 64 + q];
        uint2 w = make_uint2(pack_bf2(v.x, v.y), pack_bf2(v.z, v.w));
        *reinterpret_cast<uint2*>(
            reinterpret_cast<char*>(sA) + r * (STRIDE * 2) + q * 8) = w;
    }
#pragma unroll
    for (int i = tid; i < SX; i += NTHREADS) s_ina[i] = g_inv_na[b * SX + i];
    __syncthreads();

    {
        const int r  = tid >> 2;
        const int q0 = (tid & 3) * 64;
        const __nv_bfloat16* row = sA + r * STRIDE + q0;
        float s = 0.0f;
#pragma unroll
        for (int k = 0; k < 32; ++k) {
            float2 p = __bfloat1622float2(
                *reinterpret_cast<const __nv_bfloat162*>(row + 2 * k));
            s = fmaf(p.x, p.x, fmaf(p.y, p.y, s));
        }
        s += __shfl_xor_sync(0xffffffffu, s, 1);
        s += __shfl_xor_sync(0xffffffffu, s, 2);
        if ((tid & 3) == 0) s_inb[r] = rsqrtf(s);
    }
    cp_wait0();
    __syncthreads();

    const int g = lane >> 3, r8 = lane & 7;
    const uint32_t aA = smem_u32(sA) +
        (uint32_t)(((warp_m * 32 + (g & 1) * 8 + r8) * STRIDE + (g >> 1) * 8) * 2);
    const uint32_t aBoff =
        (uint32_t)(((warp_n * 32 + (g >> 1) * 8 + r8) * STRIDE + (g & 1) * 8) * 2);
    const uint32_t aBbuf[2] = { smem_u32(sB0) + aBoff, smem_u32(sB1) + aBoff };
    const uint32_t sBbuf[2] = { smem_u32(sB0), smem_u32(sB1) };

    float rmax[2][2];
#pragma unroll
    for (int i = 0; i < 2; ++i) rmax[i][0] = rmax[i][1] = NEG_INF;

    for (int c = 0; c < NCH; ++c) {
        if (c + 1 < NCH) {
            load_tile_async(sBbuf[(c + 1) & 1], Xg + (size_t)(c + 1) * NC * D, tid);
            cp_commit();
        }

        const uint32_t aB = aBbuf[c & 1];
        float acc[2][4][4];
#pragma unroll
        for (int mt = 0; mt < 2; ++mt)
#pragma unroll
            for (int nt = 0; nt < 4; ++nt)
#pragma unroll
                for (int q = 0; q < 4; ++q) acc[mt][nt][q] = 0.0f;

#pragma unroll 4
        for (int ks = 0; ks < KSTEPS; ++ks) {
            const uint32_t koff = (uint32_t)(ks * 16 * 2);
            uint32_t a[2][4];
#pragma unroll
            for (int mt = 0; mt < 2; ++mt)
                ldsm_x4(a[mt][0], a[mt][1], a[mt][2], a[mt][3],
                        aA + (uint32_t)(mt * 16 * STRIDE * 2) + koff);
            uint32_t bfr[4][2];
#pragma unroll
            for (int p = 0; p < 2; ++p) {
                uint32_t r0, r1, r2, r3;
                ldsm_x4(r0, r1, r2, r3,
                        aB + (uint32_t)(p * 16 * STRIDE * 2) + koff);
                bfr[p * 2][0]     = r0; bfr[p * 2][1]     = r1;
                bfr[p * 2 + 1][0] = r2; bfr[p * 2 + 1][1] = r3;
            }
#pragma unroll
            for (int mt = 0; mt < 2; ++mt)
#pragma unroll
                for (int nt = 0; nt < 4; ++nt)
                    mma_bf16(acc[mt][nt][0], acc[mt][nt][1],
                             acc[mt][nt][2], acc[mt][nt][3],
                             a[mt][0], a[mt][1], a[mt][2], a[mt][3],
                             bfr[nt][0], bfr[nt][1]);
        }

#pragma unroll
        for (int nt = 0; nt < 4; ++nt) {
            const int n0 = c * NC + warp_n * 32 + nt * 8 + (lane & 3) * 2;
            const float i0 = s_ina[n0], i1 = s_ina[n0 + 1];
#pragma unroll
            for (int mt = 0; mt < 2; ++mt) {
                rmax[mt][0] = fmaxf(rmax[mt][0],
                                    fmaxf(acc[mt][nt][0] * i0, acc[mt][nt][1] * i1));
                rmax[mt][1] = fmaxf(rmax[mt][1],
                                    fmaxf(acc[mt][nt][2] * i0, acc[mt][nt][3] * i1));
            }
        }

        if (c + 1 < NCH) {
            cp_wait0();
            __syncthreads();
        }
    }

#pragma unroll
    for (int mt = 0; mt < 2; ++mt)
#pragma unroll
        for (int rh = 0; rh < 2; ++rh) {
            float v = rmax[mt][rh];
            v = fmaxf(v, __shfl_xor_sync(0xffffffffu, v, 1));
            v = fmaxf(v, __shfl_xor_sync(0xffffffffu, v, 2));
            rmax[mt][rh] = v;
        }
    __syncthreads();
    if ((lane & 3) == 0) {
#pragma unroll
        for (int mt = 0; mt < 2; ++mt)
#pragma unroll
            for (int rh = 0; rh < 2; ++rh) {
                const int m = warp_m * 32 + mt * 16 + rh * 8 + (lane >> 2);
                red[warp_n * MT + m] = rmax[mt][rh];
            }
    }
    __syncthreads();
    if (tid < MT) {
        float v = fmaxf(fmaxf(red[tid], red[MT + tid]),
                        fmaxf(red[2 * MT + tid], red[3 * MT + tid]));
        g_simmax[b * SM_ + m0 + tid] = v * s_inb[tid];
    }
}

// ---------------------------------------------------------------------------
// 3) stage-1 top-8: grid (B, NSLICE); each CTA finds local top-8 of 512 rows.
//    Union of slice top-8s contains the global top-8.
// ---------------------------------------------------------------------------
__global__ __launch_bounds__(512)
void top8_stage1_kernel() {
    __shared__ float swv[16];
    __shared__ int   swi[16];
    __shared__ float s_wv;
    __shared__ int   s_wi;

    const int b    = blockIdx.x;
    const int sl   = blockIdx.y;
    const int tid  = threadIdx.x;
    const int wid  = tid >> 5;
    const int lane = tid & 31;
    const int m0   = sl * 512;

    float e = g_simmax[b * SM_ + m0 + tid];

    for (int k = 0; k < NCAND; ++k) {
        float v = e;
        int   i = m0 + tid;
        amax_bfly(v, i);
        if (lane == 0) { swv[wid] = v; swi[wid] = i; }
        __syncthreads();
        if (wid == 0) {
            float fv = (lane < 16) ? swv[lane] : NEG_INF;
            int   fi = (lane < 16) ? swi[lane] : 0x7fffffff;
            amax_bfly(fv, fi);
            if (lane == 0) {
                s_wv = fv; s_wi = fi;
                g_c1v[(b * NSLICE + sl) * NCAND + k] = fv;
                g_c1i[(b * NSLICE + sl) * NCAND + k] = fi;
            }
        }
        __syncthreads();
        if (m0 + tid == s_wi) e = NEG_INF;
    }
}

// ---------------------------------------------------------------------------
// 4) exact rerank halves: grid (B, NCAND/2 pairs, 2 query-halves), 512 thr.
//    Head: warp 0 reduces the 64 stage-1 entries -> global top-8 (redundant,
//    deterministic). Body: pair's 2 candidate rows in registers; each warp
//    scores 16 queries of this half.
// ---------------------------------------------------------------------------
__global__ __launch_bounds__(512)
void rerank_half_kernel(const float* __restrict__ x, const float* __restrict__ mem) {
    __shared__ int   s_cand[NCAND];
    __shared__ float s_wmax[16][2];
    __shared__ float s_invnb[2];

    const int b    = blockIdx.x;
    const int pr   = blockIdx.y;        // pair 0..3
    const int hz   = blockIdx.z;        // query half 0..1
    const int tid  = threadIdx.x;
    const int wid  = tid >> 5;
    const int lane = tid & 31;

    // ---- head: 64 -> global top-8 (warp 0; same result in every CTA) ----
    if (wid == 0) {
        float v0 = g_c1v[b * NSLICE * NCAND + lane];
        int   i0 = g_c1i[b * NSLICE * NCAND + lane];
        float v1 = g_c1v[b * NSLICE * NCAND + 32 + lane];
        int   i1 = g_c1i[b * NSLICE * NCAND + 32 + lane];
        for (int k = 0; k < NCAND; ++k) {
            float v; int i;
            if (v0 > v1 || (v0 == v1 && i0 < i1)) { v = v0; i = i0; }
            else                                  { v = v1; i = i1; }
            amax_bfly(v, i);
            if (lane == 0) s_cand[k] = i;
            if (i0 == i) v0 = NEG_INF;
            if (i1 == i) v1 = NEG_INF;
        }
    }
    __syncthreads();

    const int c0 = pr * 2;
    const int i0 = s_cand[c0];
    const int i1 = s_cand[c0 + 1];
    if (hz == 0 && tid < 2)
        g_candf[b * NCAND + c0 + tid] = (tid == 0) ? i0 : i1;

    const float4* M0 = reinterpret_cast<const float4*>(mem + ((size_t)b * SM_ + i0) * D);
    const float4* M1 = reinterpret_cast<const float4*>(mem + ((size_t)b * SM_ + i1) * D);
    const float4 m0a = M0[lane], m0b = M0[lane + 32];
    const float4 m1a = M1[lane], m1b = M1[lane + 32];

    if (wid < 2) {
        float s = wid ? dot8(m1a, m1b, m1a, m1b) : dot8(m0a, m0b, m0a, m0b);
#pragma unroll
        for (int off = 16; off; off >>= 1)
            s += __shfl_xor_sync(0xffffffffu, s, off);
        if (lane == 0) s_invnb[wid] = rsqrtf(s);
    }

    const float* Xb = x + ((size_t)b * SX + hz * (SX / 2)) * D;
    float v0 = NEG_INF, v1 = NEG_INF;
#pragma unroll 4
    for (int i = 0; i < SX / 32; ++i) {     // 16 queries per warp in this half
        const int s = wid + 16 * i;
        const float4* X = reinterpret_cast<const float4*>(Xb + (size_t)s * D);
        const float4 xa = X[lane], xb = X[lane + 32];
        float d0 = dot8(m0a, m0b, xa, xb);
        float d1 = dot8(m1a, m1b, xa, xb);
#pragma unroll
        for (int off = 16; off; off >>= 1) {
            d0 += __shfl_xor_sync(0xffffffffu, d0, off);
            d1 += __shfl_xor_sync(0xffffffffu, d1, off);
        }
        const float ina = g_inv_na[b * SX + hz * (SX / 2) + s];
        v0 = fmaxf(v0, d0 * ina);
        v1 = fmaxf(v1, d1 * ina);
    }
    if (lane == 0) { s_wmax[wid][0] = v0; s_wmax[wid][1] = v1; }
    __syncthreads();
    if (tid < 2) {
        float m = NEG_INF;
#pragma unroll
        for (int j = 0; j < 16; ++j) m = fmaxf(m, s_wmax[j][tid]);
        g_score2[(b * NCAND + c0 + tid) * 2 + hz] = m * s_invnb[tid];
    }
}

// ---------------------------------------------------------------------------
// 5) combine halves, pick top-5 of 8, gather rows + indices.
//    out layout (float32): 5 blocks of [B,D] then [B,TOPK] indices
// ---------------------------------------------------------------------------
__global__ __launch_bounds__(256)
void select_gather_kernel(const float* __restrict__ mem, float* __restrict__ out) {
    __shared__ int s_sel[TOPK];
    const int b   = blockIdx.x;
    const int tid = threadIdx.x;

    if (tid == 0) {
        float sc[NCAND];
        int   ix[NCAND];
        for (int i = 0; i < NCAND; ++i) {
            sc[i] = fmaxf(g_score2[(b * NCAND + i) * 2],
                          g_score2[(b * NCAND + i) * 2 + 1]);
            ix[i] = g_candf[b * NCAND + i];
        }
        for (int k = 0; k < TOPK; ++k) {
            int best = k;
            for (int j = k + 1; j < NCAND; ++j)
                if (sc[j] > sc[best] || (sc[j] == sc[best] && ix[j] < ix[best])) best = j;
            float ts = sc[k]; sc[k] = sc[best]; sc[best] = ts;
            int   ti = ix[k]; ix[k] = ix[best]; ix[best] = ti;
            s_sel[k] = ix[k];
        }
    }
    __syncthreads();

#pragma unroll
    for (int k = 0; k < TOPK; ++k)
        out[(size_t)k * B * D + (size_t)b * D + tid] =
            mem[((size_t)b * SM_ + s_sel[k]) * D + tid];
    if (tid < TOPK)
        out[(size_t)TOPK * B * D + b * TOPK + tid] = (float)s_sel[tid];
}

// ---------------------------------------------------------------------------
extern "C" void kernel_launch(void* const* d_in, const int* in_sizes, int n_in,
                              void* d_out, int out_size) {
    const float* x   = (const float*)d_in[0];   // [B, SX, D]
    const float* mem = (const float*)d_in[1];   // [B, SM, D]
    float* out = (float*)d_out;
    (void)in_sizes; (void)n_in; (void)out_size;

    invnorm_x_kernel<<<(B * SX) / 8, 256>>>(x);

    const int smem_bytes = (MT * STRIDE + 2 * NC * STRIDE) * 2
                         + (SX + MT + 4 * MT) * 4;               // ~208 KB dynamic
    static bool attr_set = false;   // idempotent attribute, not work caching
    if (!attr_set) {
        cudaFuncSetAttribute(simmax_mma_kernel,
                             cudaFuncAttributeMaxDynamicSharedMemorySize, smem_bytes);
        attr_set = true;
    }
    dim3 grid(SM_ / MT, B);
    simmax_mma_kernel<<<grid, NTHREADS, smem_bytes>>>(mem);

    top8_stage1_kernel<<<dim3(B, NSLICE), 512>>>();
    rerank_half_kernel<<<dim3(B, NCAND / 2, 2), 512>>>(x, mem);
    select_gather_kernel<<<B, 256>>>(mem, out);
}

// round 16
// speedup vs baseline: 1.1751x; 1.0107x over previous
#include <cuda_runtime.h>
#include <cuda_bf16.h>
#include <cstdint>

// Problem constants
#define B    32
#define SX   512
#define SM_  4096
#define D    256
#define TOPK 5
#define NCAND 8
#define NSLICE 8          // stage-1 slices per batch (512 rows each)
#define NQ    4           // query quarters for rerank

#define NEG_INF (__int_as_float(0xff800000))

// GEMM tiling
#define MT   128
#define NC   128
#define NCH  (SX / NC)
#define KSTEPS (D / 16)
#define STRIDE 264
#define NTHREADS 512

// Scratch (no allocations allowed)
__device__ float g_inv_na[B * SX];
__device__ float g_simmax[B * SM_];
__device__ float g_c1v[B * NSLICE * NCAND];   // stage-1 local top-8 values
__device__ int   g_c1i[B * NSLICE * NCAND];   // stage-1 local top-8 indices
__device__ float g_score2[B * NCAND * NQ];    // per-quarter exact partial scores
__device__ int   g_candf[B * NCAND];          // final candidate indices (ordered list)
__device__ __nv_bfloat16 g_xbf[B * SX * D];   // 8 MB

// ---------------------------------------------------------------------------
// helpers
// ---------------------------------------------------------------------------
__device__ __forceinline__ uint32_t smem_u32(const void* p) {
    return (uint32_t)__cvta_generic_to_shared(p);
}

__device__ __forceinline__ uint32_t pack_bf2(float a, float b) {
    __nv_bfloat162 h = __float22bfloat162_rn(make_float2(a, b));
    return *reinterpret_cast<uint32_t*>(&h);
}

__device__ __forceinline__ void cp16(uint32_t dst, const void* src) {
    asm volatile("cp.async.cg.shared.global [%0], [%1], 16;" :: "r"(dst), "l"(src));
}
__device__ __forceinline__ void cp_commit() {
    asm volatile("cp.async.commit_group;" ::: "memory");
}
__device__ __forceinline__ void cp_wait0() {
    asm volatile("cp.async.wait_group 0;" ::: "memory");
}

__device__ __forceinline__ void ldsm_x4(uint32_t& r0, uint32_t& r1,
                                        uint32_t& r2, uint32_t& r3, uint32_t addr) {
    asm volatile("ldmatrix.sync.aligned.m8n8.x4.shared.b16 {%0,%1,%2,%3}, [%4];"
                 : "=r"(r0), "=r"(r1), "=r"(r2), "=r"(r3) : "r"(addr));
}

__device__ __forceinline__ void mma_bf16(float& c0, float& c1, float& c2, float& c3,
                                         uint32_t a0, uint32_t a1, uint32_t a2, uint32_t a3,
                                         uint32_t b0, uint32_t b1) {
    asm volatile(
        "mma.sync.aligned.m16n8k16.row.col.f32.bf16.bf16.f32 "
        "{%0,%1,%2,%3}, {%4,%5,%6,%7}, {%8,%9}, {%0,%1,%2,%3};"
        : "+f"(c0), "+f"(c1), "+f"(c2), "+f"(c3)
        : "r"(a0), "r"(a1), "r"(a2), "r"(a3), "r"(b0), "r"(b1));
}

__device__ __forceinline__ float dot8(const float4& a0, const float4& a1,
                                      const float4& b0, const float4& b1) {
    float s = a0.x * b0.x;
    s = fmaf(a0.y, b0.y, s);
    s = fmaf(a0.z, b0.z, s);
    s = fmaf(a0.w, b0.w, s);
    s = fmaf(a1.x, b1.x, s);
    s = fmaf(a1.y, b1.y, s);
    s = fmaf(a1.z, b1.z, s);
    s = fmaf(a1.w, b1.w, s);
    return s;
}

// argmax butterfly with lowest-index tie-break (all lanes converge)
__device__ __forceinline__ void amax_bfly(float& v, int& i) {
#pragma unroll
    for (int off = 16; off; off >>= 1) {
        float ov = __shfl_xor_sync(0xffffffffu, v, off);
        int   oi = __shfl_xor_sync(0xffffffffu, i, off);
        if (ov > v || (ov == v && oi < i)) { v = ov; i = oi; }
    }
}

// ---------------------------------------------------------------------------
// 1) x only: inverse L2 norm per row + bf16 conversion (one warp per row)
// ---------------------------------------------------------------------------
__global__ void invnorm_x_kernel(const float* __restrict__ in) {
    int gwarp = (blockIdx.x * blockDim.x + threadIdx.x) >> 5;
    int lane  = threadIdx.x & 31;
    if (gwarp >= B * SX) return;
    const float4* r = reinterpret_cast<const float4*>(in + (size_t)gwarp * D);
    float4 v0 = r[lane];
    float4 v1 = r[lane + 32];

    __nv_bfloat16* dst = g_xbf + (size_t)gwarp * D;
    uint2 wa = make_uint2(pack_bf2(v0.x, v0.y), pack_bf2(v0.z, v0.w));
    uint2 wb = make_uint2(pack_bf2(v1.x, v1.y), pack_bf2(v1.z, v1.w));
    reinterpret_cast<uint64_t*>(dst)[lane]      = *reinterpret_cast<uint64_t*>(&wa);
    reinterpret_cast<uint64_t*>(dst)[lane + 32] = *reinterpret_cast<uint64_t*>(&wb);

    float s = v0.x * v0.x + v0.y * v0.y + v0.z * v0.z + v0.w * v0.w
            + v1.x * v1.x + v1.y * v1.y + v1.z * v1.z + v1.w * v1.w;
#pragma unroll
    for (int off = 16; off; off >>= 1)
        s += __shfl_xor_sync(0xffffffffu, s, off);
    if (lane == 0) g_inv_na[gwarp] = rsqrtf(s);
}

// ---------------------------------------------------------------------------
// 2) fused tensor sim-max (proven R10-R15 body, unchanged)
// ---------------------------------------------------------------------------
__device__ __forceinline__ void load_tile_async(uint32_t sdst,
                                                const __nv_bfloat16* gsrc, int tid) {
#pragma unroll
    for (int i = tid; i < MT * 32; i += NTHREADS) {
        const int r = i >> 5, c = i & 31;
        cp16(sdst + (uint32_t)(r * (STRIDE * 2) + c * 16), gsrc + (size_t)r * D + c * 8);
    }
}

__global__ __launch_bounds__(NTHREADS, 1)
void simmax_mma_kernel(const float* __restrict__ mem) {
    extern __shared__ char smem[];
    __nv_bfloat16* sA  = reinterpret_cast<__nv_bfloat16*>(smem);
    __nv_bfloat16* sB0 = sA + MT * STRIDE;
    __nv_bfloat16* sB1 = sB0 + NC * STRIDE;
    float* s_ina = reinterpret_cast<float*>(sB1 + NC * STRIDE);
    float* s_inb = s_ina + SX;
    float* red   = s_inb + MT;

    const int tid    = threadIdx.x;
    const int wid    = tid >> 5;
    const int lane   = tid & 31;
    const int b      = blockIdx.y;
    const int m0     = blockIdx.x * MT;
    const int warp_m = wid & 3;
    const int warp_n = wid >> 2;

    const float* Ag = mem + ((size_t)b * SM_ + m0) * D;
    const __nv_bfloat16* Xg = g_xbf + (size_t)b * SX * D;

    load_tile_async(smem_u32(sB0), Xg, tid);
    cp_commit();

#pragma unroll
    for (int j = 0; j < 16; ++j) {
        const int idx = j * NTHREADS + tid;
        const int r = idx >> 6, q = idx & 63;
        float4 v = reinterpret_cast<const float4*>(Ag)[(size_t)r * 64 + q];
        uint2 w = make_uint2(pack_bf2(v.x, v.y), pack_bf2(v.z, v.w));
        *reinterpret_cast<uint2*>(
            reinterpret_cast<char*>(sA) + r * (STRIDE * 2) + q * 8) = w;
    }
#pragma unroll
    for (int i = tid; i < SX; i += NTHREADS) s_ina[i] = g_inv_na[b * SX + i];
    __syncthreads();

    {
        const int r  = tid >> 2;
        const int q0 = (tid & 3) * 64;
        const __nv_bfloat16* row = sA + r * STRIDE + q0;
        float s = 0.0f;
#pragma unroll
        for (int k = 0; k < 32; ++k) {
            float2 p = __bfloat1622float2(
                *reinterpret_cast<const __nv_bfloat162*>(row + 2 * k));
            s = fmaf(p.x, p.x, fmaf(p.y, p.y, s));
        }
        s += __shfl_xor_sync(0xffffffffu, s, 1);
        s += __shfl_xor_sync(0xffffffffu, s, 2);
        if ((tid & 3) == 0) s_inb[r] = rsqrtf(s);
    }
    cp_wait0();
    __syncthreads();

    const int g = lane >> 3, r8 = lane & 7;
    const uint32_t aA = smem_u32(sA) +
        (uint32_t)(((warp_m * 32 + (g & 1) * 8 + r8) * STRIDE + (g >> 1) * 8) * 2);
    const uint32_t aBoff =
        (uint32_t)(((warp_n * 32 + (g >> 1) * 8 + r8) * STRIDE + (g & 1) * 8) * 2);
    const uint32_t aBbuf[2] = { smem_u32(sB0) + aBoff, smem_u32(sB1) + aBoff };
    const uint32_t sBbuf[2] = { smem_u32(sB0), smem_u32(sB1) };

    float rmax[2][2];
#pragma unroll
    for (int i = 0; i < 2; ++i) rmax[i][0] = rmax[i][1] = NEG_INF;

    for (int c = 0; c < NCH; ++c) {
        if (c + 1 < NCH) {
            load_tile_async(sBbuf[(c + 1) & 1], Xg + (size_t)(c + 1) * NC * D, tid);
            cp_commit();
        }

        const uint32_t aB = aBbuf[c & 1];
        float acc[2][4][4];
#pragma unroll
        for (int mt = 0; mt < 2; ++mt)
#pragma unroll
            for (int nt = 0; nt < 4; ++nt)
#pragma unroll
                for (int q = 0; q < 4; ++q) acc[mt][nt][q] = 0.0f;

#pragma unroll 4
        for (int ks = 0; ks < KSTEPS; ++ks) {
            const uint32_t koff = (uint32_t)(ks * 16 * 2);
            uint32_t a[2][4];
#pragma unroll
            for (int mt = 0; mt < 2; ++mt)
                ldsm_x4(a[mt][0], a[mt][1], a[mt][2], a[mt][3],
                        aA + (uint32_t)(mt * 16 * STRIDE * 2) + koff);
            uint32_t bfr[4][2];
#pragma unroll
            for (int p = 0; p < 2; ++p) {
                uint32_t r0, r1, r2, r3;
                ldsm_x4(r0, r1, r2, r3,
                        aB + (uint32_t)(p * 16 * STRIDE * 2) + koff);
                bfr[p * 2][0]     = r0; bfr[p * 2][1]     = r1;
                bfr[p * 2 + 1][0] = r2; bfr[p * 2 + 1][1] = r3;
            }
#pragma unroll
            for (int mt = 0; mt < 2; ++mt)
#pragma unroll
                for (int nt = 0; nt < 4; ++nt)
                    mma_bf16(acc[mt][nt][0], acc[mt][nt][1],
                             acc[mt][nt][2], acc[mt][nt][3],
                             a[mt][0], a[mt][1], a[mt][2], a[mt][3],
                             bfr[nt][0], bfr[nt][1]);
        }

#pragma unroll
        for (int nt = 0; nt < 4; ++nt) {
            const int n0 = c * NC + warp_n * 32 + nt * 8 + (lane & 3) * 2;
            const float i0 = s_ina[n0], i1 = s_ina[n0 + 1];
#pragma unroll
            for (int mt = 0; mt < 2; ++mt) {
                rmax[mt][0] = fmaxf(rmax[mt][0],
                                    fmaxf(acc[mt][nt][0] * i0, acc[mt][nt][1] * i1));
                rmax[mt][1] = fmaxf(rmax[mt][1],
                                    fmaxf(acc[mt][nt][2] * i0, acc[mt][nt][3] * i1));
            }
        }

        if (c + 1 < NCH) {
            cp_wait0();
            __syncthreads();
        }
    }

#pragma unroll
    for (int mt = 0; mt < 2; ++mt)
#pragma unroll
        for (int rh = 0; rh < 2; ++rh) {
            float v = rmax[mt][rh];
            v = fmaxf(v, __shfl_xor_sync(0xffffffffu, v, 1));
            v = fmaxf(v, __shfl_xor_sync(0xffffffffu, v, 2));
            rmax[mt][rh] = v;
        }
    __syncthreads();
    if ((lane & 3) == 0) {
#pragma unroll
        for (int mt = 0; mt < 2; ++mt)
#pragma unroll
            for (int rh = 0; rh < 2; ++rh) {
                const int m = warp_m * 32 + mt * 16 + rh * 8 + (lane >> 2);
                red[warp_n * MT + m] = rmax[mt][rh];
            }
    }
    __syncthreads();
    if (tid < MT) {
        float v = fmaxf(fmaxf(red[tid], red[MT + tid]),
                        fmaxf(red[2 * MT + tid], red[3 * MT + tid]));
        g_simmax[b * SM_ + m0 + tid] = v * s_inb[tid];
    }
}

// ---------------------------------------------------------------------------
// 3) stage-1 top-8: grid (B, NSLICE); each CTA: local top-8 of its 512 rows.
// ---------------------------------------------------------------------------
__global__ __launch_bounds__(512)
void top8_stage1_kernel() {
    __shared__ float swv[16];
    __shared__ int   swi[16];
    __shared__ int   s_wi;

    const int b    = blockIdx.x;
    const int sl   = blockIdx.y;
    const int tid  = threadIdx.x;
    const int wid  = tid >> 5;
    const int lane = tid & 31;
    const int m0   = sl * 512;

    float e = g_simmax[b * SM_ + m0 + tid];

    for (int k = 0; k < NCAND; ++k) {
        float v = e;
        int   i = m0 + tid;
        amax_bfly(v, i);
        if (lane == 0) { swv[wid] = v; swi[wid] = i; }
        __syncthreads();
        if (wid == 0) {
            float fv = (lane < 16) ? swv[lane] : NEG_INF;
            int   fi = (lane < 16) ? swi[lane] : 0x7fffffff;
            amax_bfly(fv, fi);
            if (lane == 0) {
                s_wi = fi;
                g_c1v[(b * NSLICE + sl) * NCAND + k] = fv;
                g_c1i[(b * NSLICE + sl) * NCAND + k] = fi;
            }
        }
        __syncthreads();
        if (m0 + tid == s_wi) e = NEG_INF;
    }
}

// ---------------------------------------------------------------------------
// 4) exact rerank quarters: grid (B, NCAND/2 pairs, NQ query-quarters).
//    Head: warp 0 reduces 64 stage-1 entries -> global top-8 (redundant,
//    deterministic). Body: pair rows in registers; each warp scores 8 queries.
// ---------------------------------------------------------------------------
__global__ __launch_bounds__(512)
void rerank_q_kernel(const float* __restrict__ x, const float* __restrict__ mem) {
    __shared__ int   s_cand[NCAND];
    __shared__ float s_wmax[16][2];
    __shared__ float s_invnb[2];

    const int b    = blockIdx.x;
    const int pr   = blockIdx.y;        // pair 0..3
    const int qz   = blockIdx.z;        // query quarter 0..3
    const int tid  = threadIdx.x;
    const int wid  = tid >> 5;
    const int lane = tid & 31;

    // ---- head: 64 -> global top-8 (warp 0; identical result in every CTA) ----
    if (wid == 0) {
        float v0 = g_c1v[b * NSLICE * NCAND + lane];
        int   i0 = g_c1i[b * NSLICE * NCAND + lane];
        float v1 = g_c1v[b * NSLICE * NCAND + 32 + lane];
        int   i1 = g_c1i[b * NSLICE * NCAND + 32 + lane];
        for (int k = 0; k < NCAND; ++k) {
            float v; int i;
            if (v0 > v1 || (v0 == v1 && i0 < i1)) { v = v0; i = i0; }
            else                                  { v = v1; i = i1; }
            amax_bfly(v, i);
            if (lane == 0) s_cand[k] = i;
            if (i0 == i) v0 = NEG_INF;
            if (i1 == i) v1 = NEG_INF;
        }
    }
    __syncthreads();

    const int c0 = pr * 2;
    const int i0 = s_cand[c0];
    const int i1 = s_cand[c0 + 1];
    if (qz == 0 && tid < 2)
        g_candf[b * NCAND + c0 + tid] = (tid == 0) ? i0 : i1;

    const float4* M0 = reinterpret_cast<const float4*>(mem + ((size_t)b * SM_ + i0) * D);
    const float4* M1 = reinterpret_cast<const float4*>(mem + ((size_t)b * SM_ + i1) * D);
    const float4 m0a = M0[lane], m0b = M0[lane + 32];
    const float4 m1a = M1[lane], m1b = M1[lane + 32];

    if (wid < 2) {
        float s = wid ? dot8(m1a, m1b, m1a, m1b) : dot8(m0a, m0b, m0a, m0b);
#pragma unroll
        for (int off = 16; off; off >>= 1)
            s += __shfl_xor_sync(0xffffffffu, s, off);
        if (lane == 0) s_invnb[wid] = rsqrtf(s);
    }

    const int q0 = qz * (SX / NQ);                   // 128 queries per quarter
    const float* Xb = x + ((size_t)b * SX + q0) * D;
    float v0 = NEG_INF, v1 = NEG_INF;
#pragma unroll
    for (int i = 0; i < SX / NQ / 16; ++i) {         // 8 iterations per warp
        const int s = wid + 16 * i;
        const float4* X = reinterpret_cast<const float4*>(Xb + (size_t)s * D);
        const float4 xa = X[lane], xb = X[lane + 32];
        float d0 = dot8(m0a, m0b, xa, xb);
        float d1 = dot8(m1a, m1b, xa, xb);
#pragma unroll
        for (int off = 16; off; off >>= 1) {
            d0 += __shfl_xor_sync(0xffffffffu, d0, off);
            d1 += __shfl_xor_sync(0xffffffffu, d1, off);
        }
        const float ina = g_inv_na[b * SX + q0 + s];
        v0 = fmaxf(v0, d0 * ina);
        v1 = fmaxf(v1, d1 * ina);
    }
    if (lane == 0) { s_wmax[wid][0] = v0; s_wmax[wid][1] = v1; }
    __syncthreads();
    if (tid < 2) {
        float m = NEG_INF;
#pragma unroll
        for (int j = 0; j < 16; ++j) m = fmaxf(m, s_wmax[j][tid]);
        g_score2[(b * NCAND + c0 + tid) * NQ + qz] = m * s_invnb[tid];
    }
}

// ---------------------------------------------------------------------------
// 5) combine quarters, pick top-5 of 8, gather rows + indices.
//    out layout (float32): 5 blocks of [B,D] then [B,TOPK] indices
// ---------------------------------------------------------------------------
__global__ __launch_bounds__(256)
void select_gather_kernel(const float* __restrict__ mem, float* __restrict__ out) {
    __shared__ int s_sel[TOPK];
    const int b   = blockIdx.x;
    const int tid = threadIdx.x;

    if (tid == 0) {
        float sc[NCAND];
        int   ix[NCAND];
        for (int i = 0; i < NCAND; ++i) {
            float m = g_score2[(b * NCAND + i) * NQ];
            for (int q = 1; q < NQ; ++q)
                m = fmaxf(m, g_score2[(b * NCAND + i) * NQ + q]);
            sc[i] = m;
            ix[i] = g_candf[b * NCAND + i];
        }
        for (int k = 0; k < TOPK; ++k) {
            int best = k;
            for (int j = k + 1; j < NCAND; ++j)
                if (sc[j] > sc[best] || (sc[j] == sc[best] && ix[j] < ix[best])) best = j;
            float ts = sc[k]; sc[k] = sc[best]; sc[best] = ts;
            int   ti = ix[k]; ix[k] = ix[best]; ix[best] = ti;
            s_sel[k] = ix[k];
        }
    }
    __syncthreads();

#pragma unroll
    for (int k = 0; k < TOPK; ++k)
        out[(size_t)k * B * D + (size_t)b * D + tid] =
            mem[((size_t)b * SM_ + s_sel[k]) * D + tid];
    if (tid < TOPK)
        out[(size_t)TOPK * B * D + b * TOPK + tid] = (float)s_sel[tid];
}

// ---------------------------------------------------------------------------
extern "C" void kernel_launch(void* const* d_in, const int* in_sizes, int n_in,
                              void* d_out, int out_size) {
    const float* x   = (const float*)d_in[0];   // [B, SX, D]
    const float* mem = (const float*)d_in[1];   // [B, SM, D]
    float* out = (float*)d_out;
    (void)in_sizes; (void)n_in; (void)out_size;

    invnorm_x_kernel<<<(B * SX) / 8, 256>>>(x);

    const int smem_bytes = (MT * STRIDE + 2 * NC * STRIDE) * 2
                         + (SX + MT + 4 * MT) * 4;               // ~208 KB dynamic
    static bool attr_set = false;   // idempotent attribute, not work caching
    if (!attr_set) {
        cudaFuncSetAttribute(simmax_mma_kernel,
                             cudaFuncAttributeMaxDynamicSharedMemorySize, smem_bytes);
        attr_set = true;
    }
    dim3 grid(SM_ / MT, B);
    simmax_mma_kernel<<<grid, NTHREADS, smem_bytes>>>(mem);

    top8_stage1_kernel<<<dim3(B, NSLICE), 512>>>();
    rerank_q_kernel<<<dim3(B, NCAND / 2, NQ), 512>>>(x, mem);
    select_gather_kernel<<<B, 256>>>(mem, out);
}